// round 13
// baseline (speedup 1.0000x reference)
#include <cuda_runtime.h>
#include <cuda_bf16.h>
#include <cuda_fp16.h>
#include <cstdint>

#define CC 2
#define FF 32
#define HH 1024
#define BB 16
#define SS 2048
#define SF (SS + FF)   // 2080
#define NC 16          // K chunks of 64
#define SRB 144        // smem row bytes (128 data + 16 pad)
// 3-split bf16 GEMM staging (modes 0-1): Ahi,Alo,Bhi,Blo
#define OFF_AH 0
#define OFF_AL (128 * SRB)
#define OFF_BH (256 * SRB)
#define OFF_BL (512 * SRB)
#define STGB (768 * SRB)            // 110592
#define SMEM_G (2 * STGB)           // 221184
// fp16 GEMM staging: A 128 rows + B 256 rows
#define OFF_B (128 * SRB)
#define STG_M (384 * SRB)           // 55296
#define NSTG_M 4
#define SMEM_M (NSTG_M * STG_M)     // 221184
#define NT 512
#define NTF 256                     // threads for fp16 GEMM (8 warps, 64x64 warp tile)

typedef __nv_bfloat16 bf16;
typedef __half fp16;

// ------------------------------ device scratch ----------------------------
__device__ fp16 g_hidF[(size_t)BB * SS * HH];
__device__ bf16 g_WqTH[(size_t)CC * HH * HH], g_WqTL[(size_t)CC * HH * HH];
__device__ bf16 g_WkTH[(size_t)CC * HH * HH], g_WkTL[(size_t)CC * HH * HH];
__device__ fp16 g_McTf[(size_t)CC * HH * HH];
__device__ bf16 g_embPH[(size_t)CC * 128 * HH], g_embPL[(size_t)CC * 128 * HH];  // rows>=32 stay 0
__device__ fp16 g_EPf[(size_t)CC * 128 * HH];
__device__ fp16 g_Tf[(size_t)CC * BB * SS * HH];
__device__ float g_wvs[CC * HH];
__device__ float g_vsum[(size_t)CC * BB * SS];

// ------------------------------ helpers -----------------------------------
__device__ __forceinline__ uint32_t smem_to_u32(const void* p) {
    uint32_t a;
    asm("{ .reg .u64 t; cvta.to.shared.u64 t, %1; cvt.u32.u64 %0, t; }" : "=r"(a) : "l"(p));
    return a;
}
__device__ __forceinline__ void split2(float x, bf16& h, bf16& l) {
    h = __float2bfloat16(x);
    l = __float2bfloat16(x - __bfloat162float(h));
}
__device__ __forceinline__ uint32_t packbf(bf16 a, bf16 b) {
    return (uint32_t)__bfloat16_as_ushort(a) | ((uint32_t)__bfloat16_as_ushort(b) << 16);
}
__device__ __forceinline__ uint32_t packh(float a, float b) {
    __half2 h = __floats2half2_rn(a, b);
    return *(uint32_t*)&h;
}
__device__ __forceinline__ void ldsm4(uint32_t* r, uint32_t addr) {
    asm volatile("ldmatrix.sync.aligned.m8n8.x4.shared.b16 {%0,%1,%2,%3}, [%4];"
                 : "=r"(r[0]), "=r"(r[1]), "=r"(r[2]), "=r"(r[3]) : "r"(addr));
}
__device__ __forceinline__ void mma_bf16(float* c, const uint32_t* a, uint32_t b0, uint32_t b1) {
    asm volatile(
        "mma.sync.aligned.m16n8k16.row.col.f32.bf16.bf16.f32 "
        "{%0,%1,%2,%3},{%4,%5,%6,%7},{%8,%9},{%0,%1,%2,%3};"
        : "+f"(c[0]), "+f"(c[1]), "+f"(c[2]), "+f"(c[3])
        : "r"(a[0]), "r"(a[1]), "r"(a[2]), "r"(a[3]), "r"(b0), "r"(b1));
}
__device__ __forceinline__ void mma_fp16(float* c, const uint32_t* a, uint32_t b0, uint32_t b1) {
    asm volatile(
        "mma.sync.aligned.m16n8k16.row.col.f32.f16.f16.f32 "
        "{%0,%1,%2,%3},{%4,%5,%6,%7},{%8,%9},{%0,%1,%2,%3};"
        : "+f"(c[0]), "+f"(c[1]), "+f"(c[2]), "+f"(c[3])
        : "r"(a[0]), "r"(a[1]), "r"(a[2]), "r"(a[3]), "r"(b0), "r"(b1));
}
#define CPA(s, g) asm volatile("cp.async.cg.shared.global [%0], [%1], 16;" :: "r"(s), "l"(g))
#define CPA_COMMIT() asm volatile("cp.async.commit_group;" ::: "memory")
#define CPA_WAIT3() asm volatile("cp.async.wait_group 3;" ::: "memory")
#define CPA_WAIT2() asm volatile("cp.async.wait_group 2;" ::: "memory")
#define CPA_WAIT1() asm volatile("cp.async.wait_group 1;" ::: "memory")
#define CPA_WAIT0() asm volatile("cp.async.wait_group 0;" ::: "memory")

// ------------------------------ prep kernels ------------------------------
#define HID_BLOCKS 32768   // (BB*SS*HH/4)/256
__global__ void k_cvt(const float* __restrict__ hidden, const float* __restrict__ emb) {
    int bid = blockIdx.x;
    if (bid < HID_BLOCKS) {
        size_t i = (size_t)bid * 256 + threadIdx.x;
        float4 v = ((const float4*)hidden)[i];
        ((uint32_t*)g_hidF)[2 * i] = packh(v.x, v.y);
        ((uint32_t*)g_hidF)[2 * i + 1] = packh(v.z, v.w);
    } else {
        int i = (bid - HID_BLOCKS) * 256 + threadIdx.x;
        int e = i * 4;
        int c = e / (FF * HH);
        int rem = e - c * FF * HH;
        int f = rem / HH, h = rem - f * HH;
        float4 v = ((const float4*)emb)[i];
        bf16 h0, l0, h1, l1, h2, l2, h3, l3;
        split2(v.x, h0, l0); split2(v.y, h1, l1); split2(v.z, h2, l2); split2(v.w, h3, l3);
        size_t o = ((size_t)c * 128 + f) * HH + h;
        *(uint32_t*)&g_embPH[o] = packbf(h0, h1);
        *(uint32_t*)&g_embPH[o + 2] = packbf(h2, h3);
        *(uint32_t*)&g_embPL[o] = packbf(l0, l1);
        *(uint32_t*)&g_embPL[o + 2] = packbf(l2, l3);
    }
}

__global__ void k_tsplit_both(const float* __restrict__ Wq, const float* __restrict__ Wk) {
    __shared__ float t[32][33];
    int z = blockIdx.z;
    int c = z >> 1, W = z & 1;
    const float* I = (W == 0 ? Wq : Wk) + (size_t)c * HH * HH;
    bf16* OH = (W == 0 ? g_WqTH : g_WkTH) + (size_t)c * HH * HH;
    bf16* OL = (W == 0 ? g_WqTL : g_WkTL) + (size_t)c * HH * HH;
    int x = blockIdx.x * 32 + threadIdx.x;
#pragma unroll
    for (int i = threadIdx.y; i < 32; i += 8)
        t[i][threadIdx.x] = I[(size_t)(blockIdx.y * 32 + i) * HH + x];
    __syncthreads();
    int ox = blockIdx.y * 32 + threadIdx.x;
#pragma unroll
    for (int i = threadIdx.y; i < 32; i += 8) {
        float v = t[threadIdx.x][i];
        bf16 h, l;
        split2(v, h, l);
        size_t o = (size_t)(blockIdx.x * 32 + i) * HH + ox;
        OH[o] = h;
        OL[o] = l;
    }
}

__global__ void k_wvsum(const float* __restrict__ Wv) {
    int c = blockIdx.y;
    int h = blockIdx.x * 256 + threadIdx.x;
    const float* W = Wv + (size_t)c * HH * HH;
    float a = 0.f;
#pragma unroll 8
    for (int o = 0; o < HH; ++o) a += W[(size_t)o * HH + h];
    g_wvs[c * HH + h] = a;
}

__global__ void k_vsum(const float* __restrict__ hidden) {
    int w = (blockIdx.x * blockDim.x + threadIdx.x) >> 5;
    int lane = threadIdx.x & 31;
    if (w >= BB * SS) return;
    const float* hr = hidden + (size_t)w * HH;
    float a0 = 0.f, a1 = 0.f;
#pragma unroll 4
    for (int i = lane; i < HH; i += 32) {
        float hv = hr[i];
        a0 += hv * g_wvs[i];
        a1 += hv * g_wvs[HH + i];
    }
#pragma unroll
    for (int off = 16; off; off >>= 1) {
        a0 += __shfl_down_sync(0xFFFFFFFFu, a0, off);
        a1 += __shfl_down_sync(0xFFFFFFFFu, a1, off);
    }
    if (lane == 0) {
        g_vsum[w] = a0;
        g_vsum[(size_t)BB * SS + w] = a1;
    }
}

// ------------------------------ 3-split bf16 GEMM (modes 0-1) -------------
// C[128,256] = (Ahi+Alo).(Bhi+Blo)^T, 16 warps, warp tile 64x32, 2-stage.
// MODE 0: McT (fp16 out)   1: E (fp16 out)
template <int MODE>
__global__ void __launch_bounds__(NT, 1) k_gemm() {
    extern __shared__ __align__(128) char smem[];
    const uint32_t sb = smem_to_u32(smem);
    const int tid = threadIdx.x, wid = tid >> 5, lane = tid & 31;
    const int bx = blockIdx.x, by = blockIdx.y, bz = blockIdx.z;

    const bf16 *AH, *AL, *BH, *BL;
    if (MODE == 0) {
        size_t cb = (size_t)bz * HH * HH;
        AH = g_WkTH + cb + (size_t)by * 128 * HH; AL = g_WkTL + cb + (size_t)by * 128 * HH;
        BH = g_WqTH + cb + (size_t)bx * 256 * HH; BL = g_WqTL + cb + (size_t)bx * 256 * HH;
    } else {
        AH = g_embPH + (size_t)bz * 128 * HH; AL = g_embPL + (size_t)bz * 128 * HH;
        size_t cb = (size_t)bz * HH * HH;
        BH = g_WkTH + cb + (size_t)bx * 256 * HH; BL = g_WkTL + cb + (size_t)bx * 256 * HH;
    }

    const int arow = tid >> 2, aq = tid & 3;
    const uint32_t sAOff = (uint32_t)(arow * SRB + aq * 32);
    const size_t gAOff = (size_t)arow * HH + aq * 16;
    const int brow = tid >> 1, bhalf = tid & 1;
    const uint32_t sBOff = (uint32_t)(brow * SRB + bhalf * 64);
    const size_t gBOff = (size_t)brow * HH + bhalf * 32;

    const int wm = wid >> 3, wn = wid & 7;
    const uint32_t aOff = (uint32_t)((wm * 64 + (lane & 15)) * SRB + ((lane >> 4) << 4));
    const uint32_t bOff = (uint32_t)((wn * 32 + (lane & 7) + ((lane >> 4) & 1) * 8) * SRB +
                                     (((lane >> 3) & 1) << 4));

    float acc[4][4][4] = {};

    {
#pragma unroll
        for (int i = 0; i < 2; i++) {
            CPA(sb + OFF_AH + sAOff + i * 16, AH + gAOff + i * 8);
            CPA(sb + OFF_AL + sAOff + i * 16, AL + gAOff + i * 8);
        }
#pragma unroll
        for (int i = 0; i < 4; i++) {
            CPA(sb + OFF_BH + sBOff + i * 16, BH + gBOff + i * 8);
            CPA(sb + OFF_BL + sBOff + i * 16, BL + gBOff + i * 8);
        }
        CPA_COMMIT();
    }

    for (int ck = 0; ck < NC; ck++) {
        if (ck + 1 < NC) {
            const uint32_t stg = sb + ((ck + 1) & 1) * STGB;
            const int kof = (ck + 1) * 64;
#pragma unroll
            for (int i = 0; i < 2; i++) {
                CPA(stg + OFF_AH + sAOff + i * 16, AH + gAOff + kof + i * 8);
                CPA(stg + OFF_AL + sAOff + i * 16, AL + gAOff + kof + i * 8);
            }
#pragma unroll
            for (int i = 0; i < 4; i++) {
                CPA(stg + OFF_BH + sBOff + i * 16, BH + gBOff + kof + i * 8);
                CPA(stg + OFF_BL + sBOff + i * 16, BL + gBOff + kof + i * 8);
            }
            CPA_COMMIT();
            CPA_WAIT1();
        } else {
            CPA_WAIT0();
        }
        __syncthreads();

        const uint32_t base = sb + (ck & 1) * STGB;
        const uint32_t pAH = base + OFF_AH + aOff, pAL = base + OFF_AL + aOff;
        const uint32_t pBH = base + OFF_BH + bOff, pBL = base + OFF_BL + bOff;
#pragma unroll
        for (int ka = 0; ka < 4; ka++) {
            uint32_t A[4][4], Bh[2][4], Bl[2][4];
#pragma unroll
            for (int m = 0; m < 4; m++) ldsm4(A[m], pAH + m * (16 * SRB) + ka * 32);
#pragma unroll
            for (int nb = 0; nb < 2; nb++) ldsm4(Bh[nb], pBH + nb * (16 * SRB) + ka * 32);
#pragma unroll
            for (int m = 0; m < 4; m++)
#pragma unroll
                for (int n8 = 0; n8 < 4; n8++)
                    mma_bf16(acc[m][n8], A[m], Bh[n8 >> 1][(n8 & 1) * 2], Bh[n8 >> 1][(n8 & 1) * 2 + 1]);
#pragma unroll
            for (int nb = 0; nb < 2; nb++) ldsm4(Bl[nb], pBL + nb * (16 * SRB) + ka * 32);
#pragma unroll
            for (int m = 0; m < 4; m++)
#pragma unroll
                for (int n8 = 0; n8 < 4; n8++)
                    mma_bf16(acc[m][n8], A[m], Bl[n8 >> 1][(n8 & 1) * 2], Bl[n8 >> 1][(n8 & 1) * 2 + 1]);
#pragma unroll
            for (int m = 0; m < 4; m++) ldsm4(A[m], pAL + m * (16 * SRB) + ka * 32);
#pragma unroll
            for (int m = 0; m < 4; m++)
#pragma unroll
                for (int n8 = 0; n8 < 4; n8++)
                    mma_bf16(acc[m][n8], A[m], Bh[n8 >> 1][(n8 & 1) * 2], Bh[n8 >> 1][(n8 & 1) * 2 + 1]);
        }
        __syncthreads();
    }

    // epilogue -> fp16
    const int rBase = wm * 64 + (lane >> 2);
    const int cBase = wn * 32 + (lane & 3) * 2;
    fp16* O = (MODE == 0) ? g_McTf : g_EPf;
    size_t rowB = (MODE == 0) ? (size_t)bz * HH * HH + (size_t)(by * 128) * HH
                              : (size_t)bz * 128 * HH;
#pragma unroll
    for (int m = 0; m < 4; m++) {
        int r0 = m * 16 + rBase;
#pragma unroll
        for (int n8 = 0; n8 < 4; n8++) {
            int cc = bx * 256 + cBase + n8 * 8;
            *(uint32_t*)&O[rowB + (size_t)r0 * HH + cc] = packh(acc[m][n8][0], acc[m][n8][1]);
            *(uint32_t*)&O[rowB + (size_t)(r0 + 8) * HH + cc] = packh(acc[m][n8][2], acc[m][n8][3]);
        }
    }
}

// ------------------------------ fp16 GEMM ---------------------------------
// OM 0: T = hidF . McTf^T            (fp16 out, grid: x=HH/256, y=BB*SS/128, z=CC)
// OM 1: out = ([Tf;EPf].hidF^T)*vsum (fp32 out, grid: x=SS/256, y=17, z=CC*BB)
// CTA tile 128x256, 8 warps (2x4), warp tile 64x64, 4-stage cp.async,
// fragments double-buffered across ka (LDS-traffic-minimizing shape).
template <int OM>
__global__ void __launch_bounds__(NTF, 1) k_fp16(float* __restrict__ out) {
    extern __shared__ __align__(128) char smem[];
    const uint32_t sb = smem_to_u32(smem);
    const int tid = threadIdx.x, wid = tid >> 5, lane = tid & 31;
    const int bx = blockIdx.x, by = blockIdx.y, bz = blockIdx.z;
    const int c = (OM == 1) ? (bz >> 4) : bz;
    const int b = (OM == 1) ? (bz & 15) : 0;

    const fp16 *Af, *Bf;
    if (OM == 0) {
        Af = g_hidF + (size_t)by * 128 * HH;
        Bf = g_McTf + (size_t)bz * HH * HH + (size_t)bx * 256 * HH;
    } else {
        Af = (by < 16)
            ? g_Tf + ((size_t)c * BB * SS + (size_t)b * SS + (size_t)by * 128) * HH
            : g_EPf + (size_t)c * 128 * HH;
        Bf = g_hidF + ((size_t)b * SS + (size_t)bx * 256) * HH;
    }

    // loaders (256 threads): A 2 thr/row (64B half), B 1 thr/row (128B, 8x16B)
    const int arow = tid >> 1, ahalf = tid & 1;
    const uint32_t sAOff = (uint32_t)(arow * SRB + ahalf * 64);
    const size_t gAOff = (size_t)arow * HH + ahalf * 32;
    const uint32_t sBOff = (uint32_t)(OFF_B + tid * SRB);
    const size_t gBOff = (size_t)tid * HH;

    // compute mapping: 8 warps, warp grid 2(m) x 4(n), warp tile 64x64
    const int wm = wid >> 2, wn = wid & 3;
    const uint32_t aOff = (uint32_t)((wm * 64 + (lane & 15)) * SRB + ((lane >> 4) << 4));
    const uint32_t bOff = (uint32_t)(OFF_B + (wn * 64 + (lane & 7) + ((lane >> 4) & 1) * 8) * SRB +
                                     (((lane >> 3) & 1) << 4));

    float acc[4][8][4] = {};

    // prologue: chunks 0..2 -> stages 0..2
#pragma unroll
    for (int pc = 0; pc < 3; pc++) {
        const uint32_t stg = sb + pc * STG_M;
        const int kof = pc * 64;
#pragma unroll
        for (int i = 0; i < 4; i++) CPA(stg + sAOff + i * 16, Af + gAOff + kof + i * 8);
#pragma unroll
        for (int i = 0; i < 8; i++) CPA(stg + sBOff + i * 16, Bf + gBOff + kof + i * 8);
        CPA_COMMIT();
    }

    int stage = 0;
    for (int ck = 0; ck < NC; ck++) {
        if (ck + 3 < NC) {
            const uint32_t stg = sb + ((stage + 3) & 3) * STG_M;
            const int kof = (ck + 3) * 64;
#pragma unroll
            for (int i = 0; i < 4; i++) CPA(stg + sAOff + i * 16, Af + gAOff + kof + i * 8);
#pragma unroll
            for (int i = 0; i < 8; i++) CPA(stg + sBOff + i * 16, Bf + gBOff + kof + i * 8);
            CPA_COMMIT();
            CPA_WAIT3();
        } else if (ck + 2 < NC) {
            CPA_WAIT2();
        } else if (ck + 1 < NC) {
            CPA_WAIT1();
        } else {
            CPA_WAIT0();
        }
        __syncthreads();

        const uint32_t pA = sb + stage * STG_M + aOff;
        const uint32_t pB = sb + stage * STG_M + bOff;

        uint32_t A[2][4][4], Bq[2][4][4];
#pragma unroll
        for (int m = 0; m < 4; m++) ldsm4(A[0][m], pA + m * (16 * SRB));
#pragma unroll
        for (int nb = 0; nb < 4; nb++) ldsm4(Bq[0][nb], pB + nb * (16 * SRB));
#pragma unroll
        for (int ka = 0; ka < 4; ka++) {
            const int cur = ka & 1, nxt = cur ^ 1;
            if (ka < 3) {  // prefetch next-ka fragments (independent of current MMAs)
                const uint32_t ko = (ka + 1) * 32;
#pragma unroll
                for (int m = 0; m < 4; m++) ldsm4(A[nxt][m], pA + m * (16 * SRB) + ko);
#pragma unroll
                for (int nb = 0; nb < 4; nb++) ldsm4(Bq[nxt][nb], pB + nb * (16 * SRB) + ko);
            }
#pragma unroll
            for (int m = 0; m < 4; m++)
#pragma unroll
                for (int n8 = 0; n8 < 8; n8++)
                    mma_fp16(acc[m][n8], A[cur][m],
                             Bq[cur][n8 >> 1][(n8 & 1) * 2], Bq[cur][n8 >> 1][(n8 & 1) * 2 + 1]);
        }
        __syncthreads();
        stage = (stage + 1) & 3;
    }

    // ------------------------------ epilogue --------------------------------
    const int rBase = wm * 64 + (lane >> 2);
    const int cBase = wn * 64 + (lane & 3) * 2;
    if (OM == 0) {
        size_t rowB = ((size_t)bz * BB * SS + (size_t)by * 128) * HH;
#pragma unroll
        for (int m = 0; m < 4; m++) {
            int r0 = m * 16 + rBase;
#pragma unroll
            for (int n8 = 0; n8 < 8; n8++) {
                int cc = bx * 256 + cBase + n8 * 8;
                *(uint32_t*)&g_Tf[rowB + (size_t)r0 * HH + cc] = packh(acc[m][n8][0], acc[m][n8][1]);
                *(uint32_t*)&g_Tf[rowB + (size_t)(r0 + 8) * HH + cc] = packh(acc[m][n8][2], acc[m][n8][3]);
            }
        }
    } else {
        const float* vsp = g_vsum + ((size_t)c * BB + b) * SS + bx * 256;
        float* ob = out + ((size_t)b * CC + c) * SF * SS;
#pragma unroll
        for (int m = 0; m < 4; m++) {
            int r0 = by * 128 + m * 16 + rBase;
#pragma unroll
            for (int n8 = 0; n8 < 8; n8++) {
                int cc = cBase + n8 * 8;
                float2 vs = *(const float2*)(vsp + cc);
                size_t col = (size_t)bx * 256 + cc;
                if (r0 < SF) {
                    float2 o;
                    o.x = acc[m][n8][0] * vs.x;
                    o.y = acc[m][n8][1] * vs.y;
                    *(float2*)(ob + (size_t)r0 * SS + col) = o;
                }
                if (r0 + 8 < SF) {
                    float2 o;
                    o.x = acc[m][n8][2] * vs.x;
                    o.y = acc[m][n8][3] * vs.y;
                    *(float2*)(ob + (size_t)(r0 + 8) * SS + col) = o;
                }
            }
        }
    }
}

// ------------------------------ launch ------------------------------------
extern "C" void kernel_launch(void* const* d_in, const int* in_sizes, int n_in,
                              void* d_out, int out_size) {
    const float* hidden = (const float*)d_in[0];
    const float* emb    = (const float*)d_in[1];
    const float* Wk     = (const float*)d_in[2];
    const float* Wq     = (const float*)d_in[3];
    const float* Wv     = (const float*)d_in[4];
    float* out = (float*)d_out;

    cudaFuncSetAttribute(k_gemm<0>, cudaFuncAttributeMaxDynamicSharedMemorySize, SMEM_G);
    cudaFuncSetAttribute(k_gemm<1>, cudaFuncAttributeMaxDynamicSharedMemorySize, SMEM_G);
    cudaFuncSetAttribute(k_fp16<0>, cudaFuncAttributeMaxDynamicSharedMemorySize, SMEM_M);
    cudaFuncSetAttribute(k_fp16<1>, cudaFuncAttributeMaxDynamicSharedMemorySize, SMEM_M);

    // launch order chosen so the 4th launch (ncu capture slot) is k_fp16<0> (T)
    k_cvt<<<HID_BLOCKS + 64, 256>>>(hidden, emb);                  // 1
    k_tsplit_both<<<dim3(32, 32, 2 * CC), dim3(32, 8)>>>(Wq, Wk);  // 2
    k_gemm<0><<<dim3(4, 8, CC), NT, SMEM_G>>>();                   // 3: McT
    k_fp16<0><<<dim3(4, 256, CC), NTF, SMEM_M>>>(nullptr);         // 4: T  <- ncu
    k_gemm<1><<<dim3(4, 1, CC), NT, SMEM_G>>>();                   // 5: E
    k_wvsum<<<dim3(HH / 256, CC), 256>>>(Wv);                      // 6
    k_vsum<<<(BB * SS) / 8, 256>>>(hidden);                        // 7
    k_fp16<1><<<dim3(8, 17, CC * BB), NTF, SMEM_M>>>(out);         // 8: scores
}

// round 14
// speedup vs baseline: 1.0230x; 1.0230x over previous
#include <cuda_runtime.h>
#include <cuda_bf16.h>
#include <cuda_fp16.h>
#include <cstdint>

#define CC 2
#define FF 32
#define HH 1024
#define BB 16
#define SS 2048
#define SF (SS + FF)   // 2080
// 3-split bf16 GEMM staging: K-chunk 64, SRB 144
#define NC 16
#define SRB 144
#define OFF_AH 0
#define OFF_AL (128 * SRB)
#define OFF_BH (256 * SRB)
#define OFF_BL (512 * SRB)
#define STGB (768 * SRB)            // 110592
#define SMEM_G (2 * STGB)           // 221184
// fp16 GEMM staging: K-chunk 128, SRB 272 (256B data + 16B pad)
#define NCF 8
#define SRBF 272
#define OFF_BF (128 * SRBF)
#define STG_F (384 * SRBF)          // 104448
#define SMEM_F (2 * STG_F)          // 208896
#define NT 512

typedef __nv_bfloat16 bf16;
typedef __half fp16;

// ------------------------------ device scratch ----------------------------
__device__ fp16 g_hidF[(size_t)BB * SS * HH];
__device__ bf16 g_WqTH[(size_t)CC * HH * HH], g_WqTL[(size_t)CC * HH * HH];
__device__ bf16 g_WkTH[(size_t)CC * HH * HH], g_WkTL[(size_t)CC * HH * HH];
__device__ fp16 g_McTf[(size_t)CC * HH * HH];
__device__ bf16 g_embPH[(size_t)CC * 128 * HH], g_embPL[(size_t)CC * 128 * HH];  // rows>=32 stay 0
__device__ fp16 g_EPf[(size_t)CC * 128 * HH];
__device__ fp16 g_Tf[(size_t)CC * BB * SS * HH];
__device__ float g_wvs[CC * HH];
__device__ float g_vsum[(size_t)CC * BB * SS];

// ------------------------------ helpers -----------------------------------
__device__ __forceinline__ uint32_t smem_to_u32(const void* p) {
    uint32_t a;
    asm("{ .reg .u64 t; cvta.to.shared.u64 t, %1; cvt.u32.u64 %0, t; }" : "=r"(a) : "l"(p));
    return a;
}
__device__ __forceinline__ void split2(float x, bf16& h, bf16& l) {
    h = __float2bfloat16(x);
    l = __float2bfloat16(x - __bfloat162float(h));
}
__device__ __forceinline__ uint32_t packbf(bf16 a, bf16 b) {
    return (uint32_t)__bfloat16_as_ushort(a) | ((uint32_t)__bfloat16_as_ushort(b) << 16);
}
__device__ __forceinline__ uint32_t packh(float a, float b) {
    __half2 h = __floats2half2_rn(a, b);
    return *(uint32_t*)&h;
}
__device__ __forceinline__ void ldsm4(uint32_t* r, uint32_t addr) {
    asm volatile("ldmatrix.sync.aligned.m8n8.x4.shared.b16 {%0,%1,%2,%3}, [%4];"
                 : "=r"(r[0]), "=r"(r[1]), "=r"(r[2]), "=r"(r[3]) : "r"(addr));
}
__device__ __forceinline__ void mma_bf16(float* c, const uint32_t* a, uint32_t b0, uint32_t b1) {
    asm volatile(
        "mma.sync.aligned.m16n8k16.row.col.f32.bf16.bf16.f32 "
        "{%0,%1,%2,%3},{%4,%5,%6,%7},{%8,%9},{%0,%1,%2,%3};"
        : "+f"(c[0]), "+f"(c[1]), "+f"(c[2]), "+f"(c[3])
        : "r"(a[0]), "r"(a[1]), "r"(a[2]), "r"(a[3]), "r"(b0), "r"(b1));
}
__device__ __forceinline__ void mma_fp16(float* c, const uint32_t* a, uint32_t b0, uint32_t b1) {
    asm volatile(
        "mma.sync.aligned.m16n8k16.row.col.f32.f16.f16.f32 "
        "{%0,%1,%2,%3},{%4,%5,%6,%7},{%8,%9},{%0,%1,%2,%3};"
        : "+f"(c[0]), "+f"(c[1]), "+f"(c[2]), "+f"(c[3])
        : "r"(a[0]), "r"(a[1]), "r"(a[2]), "r"(a[3]), "r"(b0), "r"(b1));
}
#define CPA(s, g) asm volatile("cp.async.cg.shared.global [%0], [%1], 16;" :: "r"(s), "l"(g))
#define CPA_COMMIT() asm volatile("cp.async.commit_group;" ::: "memory")
#define CPA_WAIT1() asm volatile("cp.async.wait_group 1;" ::: "memory")
#define CPA_WAIT0() asm volatile("cp.async.wait_group 0;" ::: "memory")

// ------------------------------ prep kernels ------------------------------
#define HID_BLOCKS 32768   // (BB*SS*HH/4)/256
__global__ void k_cvt(const float* __restrict__ hidden, const float* __restrict__ emb) {
    int bid = blockIdx.x;
    if (bid < HID_BLOCKS) {
        size_t i = (size_t)bid * 256 + threadIdx.x;
        float4 v = ((const float4*)hidden)[i];
        ((uint32_t*)g_hidF)[2 * i] = packh(v.x, v.y);
        ((uint32_t*)g_hidF)[2 * i + 1] = packh(v.z, v.w);
    } else {
        int i = (bid - HID_BLOCKS) * 256 + threadIdx.x;
        int e = i * 4;
        int c = e / (FF * HH);
        int rem = e - c * FF * HH;
        int f = rem / HH, h = rem - f * HH;
        float4 v = ((const float4*)emb)[i];
        bf16 h0, l0, h1, l1, h2, l2, h3, l3;
        split2(v.x, h0, l0); split2(v.y, h1, l1); split2(v.z, h2, l2); split2(v.w, h3, l3);
        size_t o = ((size_t)c * 128 + f) * HH + h;
        *(uint32_t*)&g_embPH[o] = packbf(h0, h1);
        *(uint32_t*)&g_embPH[o + 2] = packbf(h2, h3);
        *(uint32_t*)&g_embPL[o] = packbf(l0, l1);
        *(uint32_t*)&g_embPL[o + 2] = packbf(l2, l3);
    }
}

__global__ void k_tsplit_both(const float* __restrict__ Wq, const float* __restrict__ Wk) {
    __shared__ float t[32][33];
    int z = blockIdx.z;
    int c = z >> 1, W = z & 1;
    const float* I = (W == 0 ? Wq : Wk) + (size_t)c * HH * HH;
    bf16* OH = (W == 0 ? g_WqTH : g_WkTH) + (size_t)c * HH * HH;
    bf16* OL = (W == 0 ? g_WqTL : g_WkTL) + (size_t)c * HH * HH;
    int x = blockIdx.x * 32 + threadIdx.x;
#pragma unroll
    for (int i = threadIdx.y; i < 32; i += 8)
        t[i][threadIdx.x] = I[(size_t)(blockIdx.y * 32 + i) * HH + x];
    __syncthreads();
    int ox = blockIdx.y * 32 + threadIdx.x;
#pragma unroll
    for (int i = threadIdx.y; i < 32; i += 8) {
        float v = t[threadIdx.x][i];
        bf16 h, l;
        split2(v, h, l);
        size_t o = (size_t)(blockIdx.x * 32 + i) * HH + ox;
        OH[o] = h;
        OL[o] = l;
    }
}

__global__ void k_wvsum(const float* __restrict__ Wv) {
    int c = blockIdx.y;
    int h = blockIdx.x * 256 + threadIdx.x;
    const float* W = Wv + (size_t)c * HH * HH;
    float a = 0.f;
#pragma unroll 8
    for (int o = 0; o < HH; ++o) a += W[(size_t)o * HH + h];
    g_wvs[c * HH + h] = a;
}

__global__ void k_vsum(const float* __restrict__ hidden) {
    int w = (blockIdx.x * blockDim.x + threadIdx.x) >> 5;
    int lane = threadIdx.x & 31;
    if (w >= BB * SS) return;
    const float* hr = hidden + (size_t)w * HH;
    float a0 = 0.f, a1 = 0.f;
#pragma unroll 4
    for (int i = lane; i < HH; i += 32) {
        float hv = hr[i];
        a0 += hv * g_wvs[i];
        a1 += hv * g_wvs[HH + i];
    }
#pragma unroll
    for (int off = 16; off; off >>= 1) {
        a0 += __shfl_down_sync(0xFFFFFFFFu, a0, off);
        a1 += __shfl_down_sync(0xFFFFFFFFu, a1, off);
    }
    if (lane == 0) {
        g_vsum[w] = a0;
        g_vsum[(size_t)BB * SS + w] = a1;
    }
}

// ------------------------------ 3-split bf16 GEMM (modes 0-1) -------------
// C[128,256] = (Ahi+Alo).(Bhi+Blo)^T, 16 warps, warp tile 64x32, 2-stage.
// MODE 0: McT (fp16 out)   1: E (fp16 out)
template <int MODE>
__global__ void __launch_bounds__(NT, 1) k_gemm() {
    extern __shared__ __align__(128) char smem[];
    const uint32_t sb = smem_to_u32(smem);
    const int tid = threadIdx.x, wid = tid >> 5, lane = tid & 31;
    const int bx = blockIdx.x, by = blockIdx.y, bz = blockIdx.z;

    const bf16 *AH, *AL, *BH, *BL;
    if (MODE == 0) {
        size_t cb = (size_t)bz * HH * HH;
        AH = g_WkTH + cb + (size_t)by * 128 * HH; AL = g_WkTL + cb + (size_t)by * 128 * HH;
        BH = g_WqTH + cb + (size_t)bx * 256 * HH; BL = g_WqTL + cb + (size_t)bx * 256 * HH;
    } else {
        AH = g_embPH + (size_t)bz * 128 * HH; AL = g_embPL + (size_t)bz * 128 * HH;
        size_t cb = (size_t)bz * HH * HH;
        BH = g_WkTH + cb + (size_t)bx * 256 * HH; BL = g_WkTL + cb + (size_t)bx * 256 * HH;
    }

    const int arow = tid >> 2, aq = tid & 3;
    const uint32_t sAOff = (uint32_t)(arow * SRB + aq * 32);
    const size_t gAOff = (size_t)arow * HH + aq * 16;
    const int brow = tid >> 1, bhalf = tid & 1;
    const uint32_t sBOff = (uint32_t)(brow * SRB + bhalf * 64);
    const size_t gBOff = (size_t)brow * HH + bhalf * 32;

    const int wm = wid >> 3, wn = wid & 7;
    const uint32_t aOff = (uint32_t)((wm * 64 + (lane & 15)) * SRB + ((lane >> 4) << 4));
    const uint32_t bOff = (uint32_t)((wn * 32 + (lane & 7) + ((lane >> 4) & 1) * 8) * SRB +
                                     (((lane >> 3) & 1) << 4));

    float acc[4][4][4] = {};

    {
#pragma unroll
        for (int i = 0; i < 2; i++) {
            CPA(sb + OFF_AH + sAOff + i * 16, AH + gAOff + i * 8);
            CPA(sb + OFF_AL + sAOff + i * 16, AL + gAOff + i * 8);
        }
#pragma unroll
        for (int i = 0; i < 4; i++) {
            CPA(sb + OFF_BH + sBOff + i * 16, BH + gBOff + i * 8);
            CPA(sb + OFF_BL + sBOff + i * 16, BL + gBOff + i * 8);
        }
        CPA_COMMIT();
    }

    for (int ck = 0; ck < NC; ck++) {
        if (ck + 1 < NC) {
            const uint32_t stg = sb + ((ck + 1) & 1) * STGB;
            const int kof = (ck + 1) * 64;
#pragma unroll
            for (int i = 0; i < 2; i++) {
                CPA(stg + OFF_AH + sAOff + i * 16, AH + gAOff + kof + i * 8);
                CPA(stg + OFF_AL + sAOff + i * 16, AL + gAOff + kof + i * 8);
            }
#pragma unroll
            for (int i = 0; i < 4; i++) {
                CPA(stg + OFF_BH + sBOff + i * 16, BH + gBOff + kof + i * 8);
                CPA(stg + OFF_BL + sBOff + i * 16, BL + gBOff + kof + i * 8);
            }
            CPA_COMMIT();
            CPA_WAIT1();
        } else {
            CPA_WAIT0();
        }
        __syncthreads();

        const uint32_t base = sb + (ck & 1) * STGB;
        const uint32_t pAH = base + OFF_AH + aOff, pAL = base + OFF_AL + aOff;
        const uint32_t pBH = base + OFF_BH + bOff, pBL = base + OFF_BL + bOff;
#pragma unroll
        for (int ka = 0; ka < 4; ka++) {
            uint32_t A[4][4], Bh[2][4], Bl[2][4];
#pragma unroll
            for (int m = 0; m < 4; m++) ldsm4(A[m], pAH + m * (16 * SRB) + ka * 32);
#pragma unroll
            for (int nb = 0; nb < 2; nb++) ldsm4(Bh[nb], pBH + nb * (16 * SRB) + ka * 32);
#pragma unroll
            for (int m = 0; m < 4; m++)
#pragma unroll
                for (int n8 = 0; n8 < 4; n8++)
                    mma_bf16(acc[m][n8], A[m], Bh[n8 >> 1][(n8 & 1) * 2], Bh[n8 >> 1][(n8 & 1) * 2 + 1]);
#pragma unroll
            for (int nb = 0; nb < 2; nb++) ldsm4(Bl[nb], pBL + nb * (16 * SRB) + ka * 32);
#pragma unroll
            for (int m = 0; m < 4; m++)
#pragma unroll
                for (int n8 = 0; n8 < 4; n8++)
                    mma_bf16(acc[m][n8], A[m], Bl[n8 >> 1][(n8 & 1) * 2], Bl[n8 >> 1][(n8 & 1) * 2 + 1]);
#pragma unroll
            for (int m = 0; m < 4; m++) ldsm4(A[m], pAL + m * (16 * SRB) + ka * 32);
#pragma unroll
            for (int m = 0; m < 4; m++)
#pragma unroll
                for (int n8 = 0; n8 < 4; n8++)
                    mma_bf16(acc[m][n8], A[m], Bh[n8 >> 1][(n8 & 1) * 2], Bh[n8 >> 1][(n8 & 1) * 2 + 1]);
        }
        __syncthreads();
    }

    // epilogue -> fp16
    const int rBase = wm * 64 + (lane >> 2);
    const int cBase = wn * 32 + (lane & 3) * 2;
    fp16* O = (MODE == 0) ? g_McTf : g_EPf;
    size_t rowB = (MODE == 0) ? (size_t)bz * HH * HH + (size_t)(by * 128) * HH
                              : (size_t)bz * 128 * HH;
#pragma unroll
    for (int m = 0; m < 4; m++) {
        int r0 = m * 16 + rBase;
#pragma unroll
        for (int n8 = 0; n8 < 4; n8++) {
            int cc = bx * 256 + cBase + n8 * 8;
            *(uint32_t*)&O[rowB + (size_t)r0 * HH + cc] = packh(acc[m][n8][0], acc[m][n8][1]);
            *(uint32_t*)&O[rowB + (size_t)(r0 + 8) * HH + cc] = packh(acc[m][n8][2], acc[m][n8][3]);
        }
    }
}

// ------------------------------ fp16 GEMM ---------------------------------
// OM 0: T = hidF . McTf^T            (fp16 out, grid: x=HH/256, y=BB*SS/128, z=CC)
// OM 1: out = ([Tf;EPf].hidF^T)*vsum (fp32 out, grid: x=SS/256, y=17, z=CC*BB)
// CTA tile 128x256, 16 warps (2x8), warp tile 64x32, K-chunk 128, 2 stages.
template <int OM>
__global__ void __launch_bounds__(NT, 1) k_fp16(float* __restrict__ out) {
    extern __shared__ __align__(128) char smem[];
    const uint32_t sb = smem_to_u32(smem);
    const int tid = threadIdx.x, wid = tid >> 5, lane = tid & 31;
    const int bx = blockIdx.x, by = blockIdx.y, bz = blockIdx.z;
    const int c = (OM == 1) ? (bz >> 4) : bz;
    const int b = (OM == 1) ? (bz & 15) : 0;

    const fp16 *Af, *Bf;
    if (OM == 0) {
        Af = g_hidF + (size_t)by * 128 * HH;
        Bf = g_McTf + (size_t)bz * HH * HH + (size_t)bx * 256 * HH;
    } else {
        Af = (by < 16)
            ? g_Tf + ((size_t)c * BB * SS + (size_t)b * SS + (size_t)by * 128) * HH
            : g_EPf + (size_t)c * 128 * HH;
        Bf = g_hidF + ((size_t)b * SS + (size_t)bx * 256) * HH;
    }

    // loaders (512 thr, 256B rows): A 4 thr/row (64B quarter), B 2 thr/row (128B half)
    const int arow = tid >> 2, aq = tid & 3;
    const uint32_t sAOff = (uint32_t)(arow * SRBF + aq * 64);
    const size_t gAOff = (size_t)arow * HH + aq * 32;
    const int brow = tid >> 1, bhalf = tid & 1;
    const uint32_t sBOff = (uint32_t)(OFF_BF + brow * SRBF + bhalf * 128);
    const size_t gBOff = (size_t)brow * HH + bhalf * 64;

    // compute mapping: warp tile 64x32
    const int wm = wid >> 3, wn = wid & 7;
    const uint32_t aOff = (uint32_t)((wm * 64 + (lane & 15)) * SRBF + ((lane >> 4) << 4));
    const uint32_t bOff = (uint32_t)(OFF_BF + (wn * 32 + (lane & 7) + ((lane >> 4) & 1) * 8) * SRBF +
                                     (((lane >> 3) & 1) << 4));

    float acc[4][4][4] = {};

    // prologue: chunk 0 -> stage 0
    {
#pragma unroll
        for (int i = 0; i < 4; i++) CPA(sb + sAOff + i * 16, Af + gAOff + i * 8);
#pragma unroll
        for (int i = 0; i < 8; i++) CPA(sb + sBOff + i * 16, Bf + gBOff + i * 8);
        CPA_COMMIT();
    }

    for (int ck = 0; ck < NCF; ck++) {
        if (ck + 1 < NCF) {
            const uint32_t stg = sb + ((ck + 1) & 1) * STG_F;
            const int kof = (ck + 1) * 128;
#pragma unroll
            for (int i = 0; i < 4; i++) CPA(stg + sAOff + i * 16, Af + gAOff + kof + i * 8);
#pragma unroll
            for (int i = 0; i < 8; i++) CPA(stg + sBOff + i * 16, Bf + gBOff + kof + i * 8);
            CPA_COMMIT();
            CPA_WAIT1();
        } else {
            CPA_WAIT0();
        }
        __syncthreads();

        const uint32_t pA = sb + (ck & 1) * STG_F + aOff;
        const uint32_t pB = sb + (ck & 1) * STG_F + bOff;

        uint32_t A[2][4][4], Bq[2][2][4];
#pragma unroll
        for (int m = 0; m < 4; m++) ldsm4(A[0][m], pA + m * (16 * SRBF));
#pragma unroll
        for (int nb = 0; nb < 2; nb++) ldsm4(Bq[0][nb], pB + nb * (16 * SRBF));
#pragma unroll
        for (int ka = 0; ka < 8; ka++) {
            const int cur = ka & 1, nxt = cur ^ 1;
            if (ka < 7) {  // prefetch next-ka fragments
                const uint32_t ko = (ka + 1) * 32;
#pragma unroll
                for (int m = 0; m < 4; m++) ldsm4(A[nxt][m], pA + m * (16 * SRBF) + ko);
#pragma unroll
                for (int nb = 0; nb < 2; nb++) ldsm4(Bq[nxt][nb], pB + nb * (16 * SRBF) + ko);
            }
#pragma unroll
            for (int m = 0; m < 4; m++)
#pragma unroll
                for (int n8 = 0; n8 < 4; n8++)
                    mma_fp16(acc[m][n8], A[cur][m],
                             Bq[cur][n8 >> 1][(n8 & 1) * 2], Bq[cur][n8 >> 1][(n8 & 1) * 2 + 1]);
        }
        __syncthreads();
    }

    // ------------------------------ epilogue --------------------------------
    const int rBase = wm * 64 + (lane >> 2);
    const int cBase = wn * 32 + (lane & 3) * 2;
    if (OM == 0) {
        size_t rowB = ((size_t)bz * BB * SS + (size_t)by * 128) * HH;
#pragma unroll
        for (int m = 0; m < 4; m++) {
            int r0 = m * 16 + rBase;
#pragma unroll
            for (int n8 = 0; n8 < 4; n8++) {
                int cc = bx * 256 + cBase + n8 * 8;
                *(uint32_t*)&g_Tf[rowB + (size_t)r0 * HH + cc] = packh(acc[m][n8][0], acc[m][n8][1]);
                *(uint32_t*)&g_Tf[rowB + (size_t)(r0 + 8) * HH + cc] = packh(acc[m][n8][2], acc[m][n8][3]);
            }
        }
    } else {
        const float* vsp = g_vsum + ((size_t)c * BB + b) * SS + bx * 256;
        float* ob = out + ((size_t)b * CC + c) * SF * SS;
#pragma unroll
        for (int m = 0; m < 4; m++) {
            int r0 = by * 128 + m * 16 + rBase;
#pragma unroll
            for (int n8 = 0; n8 < 4; n8++) {
                int cc = cBase + n8 * 8;
                float2 vs = *(const float2*)(vsp + cc);
                size_t col = (size_t)bx * 256 + cc;
                if (r0 < SF) {
                    float2 o;
                    o.x = acc[m][n8][0] * vs.x;
                    o.y = acc[m][n8][1] * vs.y;
                    *(float2*)(ob + (size_t)r0 * SS + col) = o;
                }
                if (r0 + 8 < SF) {
                    float2 o;
                    o.x = acc[m][n8][2] * vs.x;
                    o.y = acc[m][n8][3] * vs.y;
                    *(float2*)(ob + (size_t)(r0 + 8) * SS + col) = o;
                }
            }
        }
    }
}

// ------------------------------ launch ------------------------------------
extern "C" void kernel_launch(void* const* d_in, const int* in_sizes, int n_in,
                              void* d_out, int out_size) {
    const float* hidden = (const float*)d_in[0];
    const float* emb    = (const float*)d_in[1];
    const float* Wk     = (const float*)d_in[2];
    const float* Wq     = (const float*)d_in[3];
    const float* Wv     = (const float*)d_in[4];
    float* out = (float*)d_out;

    cudaFuncSetAttribute(k_gemm<0>, cudaFuncAttributeMaxDynamicSharedMemorySize, SMEM_G);
    cudaFuncSetAttribute(k_gemm<1>, cudaFuncAttributeMaxDynamicSharedMemorySize, SMEM_G);
    cudaFuncSetAttribute(k_fp16<0>, cudaFuncAttributeMaxDynamicSharedMemorySize, SMEM_F);
    cudaFuncSetAttribute(k_fp16<1>, cudaFuncAttributeMaxDynamicSharedMemorySize, SMEM_F);

    // launch order chosen so the 4th launch (ncu capture slot) is k_fp16<0> (T)
    k_cvt<<<HID_BLOCKS + 64, 256>>>(hidden, emb);                  // 1
    k_tsplit_both<<<dim3(32, 32, 2 * CC), dim3(32, 8)>>>(Wq, Wk);  // 2
    k_gemm<0><<<dim3(4, 8, CC), NT, SMEM_G>>>();                   // 3: McT
    k_fp16<0><<<dim3(4, 256, CC), NT, SMEM_F>>>(nullptr);          // 4: T  <- ncu
    k_gemm<1><<<dim3(4, 1, CC), NT, SMEM_G>>>();                   // 5: E
    k_wvsum<<<dim3(HH / 256, CC), 256>>>(Wv);                      // 6
    k_vsum<<<(BB * SS) / 8, 256>>>(hidden);                        // 7
    k_fp16<1><<<dim3(8, 17, CC * BB), NT, SMEM_F>>>(out);          // 8: scores
}

// round 15
// speedup vs baseline: 1.1177x; 1.0926x over previous
#include <cuda_runtime.h>
#include <cuda_bf16.h>
#include <cuda_fp16.h>
#include <cstdint>

#define CC 2
#define FF 32
#define HH 1024
#define BB 16
#define SS 2048
#define SF (SS + FF)   // 2080
#define NC 16          // K chunks of 64
#define SRB 144        // smem row bytes (128 data + 16 pad)
// 3-split bf16 GEMM staging: Ahi,Alo,Bhi,Blo (tile 128x256)
#define OFF_AH 0
#define OFF_AL (128 * SRB)
#define OFF_BH (256 * SRB)
#define OFF_BL (512 * SRB)
#define STGB (768 * SRB)            // 110592
#define SMEM_G (2 * STGB)           // 221184
#define NT 512
// fp16 GEMM staging (tile 128x128): A 128 rows + B 128 rows, 3 stages, 2 CTAs/SM
#define OFF_BF (128 * SRB)
#define STG_F (256 * SRB)           // 36864
#define NSTG_F 3
#define SMEM_F (NSTG_F * STG_F)     // 110592
#define NTF 256

typedef __nv_bfloat16 bf16;
typedef __half fp16;

// ------------------------------ device scratch ----------------------------
__device__ fp16 g_hidF[(size_t)BB * SS * HH];
__device__ bf16 g_WqTH[(size_t)CC * HH * HH], g_WqTL[(size_t)CC * HH * HH];
__device__ bf16 g_WkTH[(size_t)CC * HH * HH], g_WkTL[(size_t)CC * HH * HH];
__device__ fp16 g_McTf[(size_t)CC * HH * HH];
__device__ bf16 g_embPH[(size_t)CC * 128 * HH], g_embPL[(size_t)CC * 128 * HH];  // rows>=32 stay 0
__device__ fp16 g_EPf[(size_t)CC * 128 * HH];
__device__ fp16 g_Tf[(size_t)CC * BB * SS * HH];
__device__ float g_wvs[CC * HH];
__device__ float g_vsum[(size_t)CC * BB * SS];

// ------------------------------ helpers -----------------------------------
__device__ __forceinline__ uint32_t smem_to_u32(const void* p) {
    uint32_t a;
    asm("{ .reg .u64 t; cvta.to.shared.u64 t, %1; cvt.u32.u64 %0, t; }" : "=r"(a) : "l"(p));
    return a;
}
__device__ __forceinline__ void split2(float x, bf16& h, bf16& l) {
    h = __float2bfloat16(x);
    l = __float2bfloat16(x - __bfloat162float(h));
}
__device__ __forceinline__ uint32_t packbf(bf16 a, bf16 b) {
    return (uint32_t)__bfloat16_as_ushort(a) | ((uint32_t)__bfloat16_as_ushort(b) << 16);
}
__device__ __forceinline__ uint32_t packh(float a, float b) {
    __half2 h = __floats2half2_rn(a, b);
    return *(uint32_t*)&h;
}
__device__ __forceinline__ void ldsm4(uint32_t* r, uint32_t addr) {
    asm volatile("ldmatrix.sync.aligned.m8n8.x4.shared.b16 {%0,%1,%2,%3}, [%4];"
                 : "=r"(r[0]), "=r"(r[1]), "=r"(r[2]), "=r"(r[3]) : "r"(addr));
}
__device__ __forceinline__ void mma_bf16(float* c, const uint32_t* a, uint32_t b0, uint32_t b1) {
    asm volatile(
        "mma.sync.aligned.m16n8k16.row.col.f32.bf16.bf16.f32 "
        "{%0,%1,%2,%3},{%4,%5,%6,%7},{%8,%9},{%0,%1,%2,%3};"
        : "+f"(c[0]), "+f"(c[1]), "+f"(c[2]), "+f"(c[3])
        : "r"(a[0]), "r"(a[1]), "r"(a[2]), "r"(a[3]), "r"(b0), "r"(b1));
}
__device__ __forceinline__ void mma_fp16(float* c, const uint32_t* a, uint32_t b0, uint32_t b1) {
    asm volatile(
        "mma.sync.aligned.m16n8k16.row.col.f32.f16.f16.f32 "
        "{%0,%1,%2,%3},{%4,%5,%6,%7},{%8,%9},{%0,%1,%2,%3};"
        : "+f"(c[0]), "+f"(c[1]), "+f"(c[2]), "+f"(c[3])
        : "r"(a[0]), "r"(a[1]), "r"(a[2]), "r"(a[3]), "r"(b0), "r"(b1));
}
#define CPA(s, g) asm volatile("cp.async.cg.shared.global [%0], [%1], 16;" :: "r"(s), "l"(g))
#define CPA_COMMIT() asm volatile("cp.async.commit_group;" ::: "memory")
#define CPA_WAIT2() asm volatile("cp.async.wait_group 2;" ::: "memory")
#define CPA_WAIT1() asm volatile("cp.async.wait_group 1;" ::: "memory")
#define CPA_WAIT0() asm volatile("cp.async.wait_group 0;" ::: "memory")

// ------------------------------ prep kernels ------------------------------
#define HID_BLOCKS 32768   // (BB*SS*HH/4)/256
__global__ void k_cvt(const float* __restrict__ hidden, const float* __restrict__ emb) {
    int bid = blockIdx.x;
    if (bid < HID_BLOCKS) {
        size_t i = (size_t)bid * 256 + threadIdx.x;
        float4 v = ((const float4*)hidden)[i];
        ((uint32_t*)g_hidF)[2 * i] = packh(v.x, v.y);
        ((uint32_t*)g_hidF)[2 * i + 1] = packh(v.z, v.w);
    } else {
        int i = (bid - HID_BLOCKS) * 256 + threadIdx.x;
        int e = i * 4;
        int c = e / (FF * HH);
        int rem = e - c * FF * HH;
        int f = rem / HH, h = rem - f * HH;
        float4 v = ((const float4*)emb)[i];
        bf16 h0, l0, h1, l1, h2, l2, h3, l3;
        split2(v.x, h0, l0); split2(v.y, h1, l1); split2(v.z, h2, l2); split2(v.w, h3, l3);
        size_t o = ((size_t)c * 128 + f) * HH + h;
        *(uint32_t*)&g_embPH[o] = packbf(h0, h1);
        *(uint32_t*)&g_embPH[o + 2] = packbf(h2, h3);
        *(uint32_t*)&g_embPL[o] = packbf(l0, l1);
        *(uint32_t*)&g_embPL[o + 2] = packbf(l2, l3);
    }
}

__global__ void k_tsplit_both(const float* __restrict__ Wq, const float* __restrict__ Wk) {
    __shared__ float t[32][33];
    int z = blockIdx.z;
    int c = z >> 1, W = z & 1;
    const float* I = (W == 0 ? Wq : Wk) + (size_t)c * HH * HH;
    bf16* OH = (W == 0 ? g_WqTH : g_WkTH) + (size_t)c * HH * HH;
    bf16* OL = (W == 0 ? g_WqTL : g_WkTL) + (size_t)c * HH * HH;
    int x = blockIdx.x * 32 + threadIdx.x;
#pragma unroll
    for (int i = threadIdx.y; i < 32; i += 8)
        t[i][threadIdx.x] = I[(size_t)(blockIdx.y * 32 + i) * HH + x];
    __syncthreads();
    int ox = blockIdx.y * 32 + threadIdx.x;
#pragma unroll
    for (int i = threadIdx.y; i < 32; i += 8) {
        float v = t[threadIdx.x][i];
        bf16 h, l;
        split2(v, h, l);
        size_t o = (size_t)(blockIdx.x * 32 + i) * HH + ox;
        OH[o] = h;
        OL[o] = l;
    }
}

__global__ void k_wvsum(const float* __restrict__ Wv) {
    int c = blockIdx.y;
    int h = blockIdx.x * 256 + threadIdx.x;
    const float* W = Wv + (size_t)c * HH * HH;
    float a = 0.f;
#pragma unroll 8
    for (int o = 0; o < HH; ++o) a += W[(size_t)o * HH + h];
    g_wvs[c * HH + h] = a;
}

__global__ void k_vsum(const float* __restrict__ hidden) {
    int w = (blockIdx.x * blockDim.x + threadIdx.x) >> 5;
    int lane = threadIdx.x & 31;
    if (w >= BB * SS) return;
    const float* hr = hidden + (size_t)w * HH;
    float a0 = 0.f, a1 = 0.f;
#pragma unroll 4
    for (int i = lane; i < HH; i += 32) {
        float hv = hr[i];
        a0 += hv * g_wvs[i];
        a1 += hv * g_wvs[HH + i];
    }
#pragma unroll
    for (int off = 16; off; off >>= 1) {
        a0 += __shfl_down_sync(0xFFFFFFFFu, a0, off);
        a1 += __shfl_down_sync(0xFFFFFFFFu, a1, off);
    }
    if (lane == 0) {
        g_vsum[w] = a0;
        g_vsum[(size_t)BB * SS + w] = a1;
    }
}

// ------------------------------ 3-split bf16 GEMM (modes 0-1) -------------
// C[128,256] = (Ahi+Alo).(Bhi+Blo)^T, 16 warps, warp tile 64x32, 2-stage.
// MODE 0: McT (fp16 out)   1: E (fp16 out)
template <int MODE>
__global__ void __launch_bounds__(NT, 1) k_gemm() {
    extern __shared__ __align__(128) char smem[];
    const uint32_t sb = smem_to_u32(smem);
    const int tid = threadIdx.x, wid = tid >> 5, lane = tid & 31;
    const int bx = blockIdx.x, by = blockIdx.y, bz = blockIdx.z;

    const bf16 *AH, *AL, *BH, *BL;
    if (MODE == 0) {
        size_t cb = (size_t)bz * HH * HH;
        AH = g_WkTH + cb + (size_t)by * 128 * HH; AL = g_WkTL + cb + (size_t)by * 128 * HH;
        BH = g_WqTH + cb + (size_t)bx * 256 * HH; BL = g_WqTL + cb + (size_t)bx * 256 * HH;
    } else {
        AH = g_embPH + (size_t)bz * 128 * HH; AL = g_embPL + (size_t)bz * 128 * HH;
        size_t cb = (size_t)bz * HH * HH;
        BH = g_WkTH + cb + (size_t)bx * 256 * HH; BL = g_WkTL + cb + (size_t)bx * 256 * HH;
    }

    const int arow = tid >> 2, aq = tid & 3;
    const uint32_t sAOff = (uint32_t)(arow * SRB + aq * 32);
    const size_t gAOff = (size_t)arow * HH + aq * 16;
    const int brow = tid >> 1, bhalf = tid & 1;
    const uint32_t sBOff = (uint32_t)(brow * SRB + bhalf * 64);
    const size_t gBOff = (size_t)brow * HH + bhalf * 32;

    const int wm = wid >> 3, wn = wid & 7;
    const uint32_t aOff = (uint32_t)((wm * 64 + (lane & 15)) * SRB + ((lane >> 4) << 4));
    const uint32_t bOff = (uint32_t)((wn * 32 + (lane & 7) + ((lane >> 4) & 1) * 8) * SRB +
                                     (((lane >> 3) & 1) << 4));

    float acc[4][4][4] = {};

    {
#pragma unroll
        for (int i = 0; i < 2; i++) {
            CPA(sb + OFF_AH + sAOff + i * 16, AH + gAOff + i * 8);
            CPA(sb + OFF_AL + sAOff + i * 16, AL + gAOff + i * 8);
        }
#pragma unroll
        for (int i = 0; i < 4; i++) {
            CPA(sb + OFF_BH + sBOff + i * 16, BH + gBOff + i * 8);
            CPA(sb + OFF_BL + sBOff + i * 16, BL + gBOff + i * 8);
        }
        CPA_COMMIT();
    }

    for (int ck = 0; ck < NC; ck++) {
        if (ck + 1 < NC) {
            const uint32_t stg = sb + ((ck + 1) & 1) * STGB;
            const int kof = (ck + 1) * 64;
#pragma unroll
            for (int i = 0; i < 2; i++) {
                CPA(stg + OFF_AH + sAOff + i * 16, AH + gAOff + kof + i * 8);
                CPA(stg + OFF_AL + sAOff + i * 16, AL + gAOff + kof + i * 8);
            }
#pragma unroll
            for (int i = 0; i < 4; i++) {
                CPA(stg + OFF_BH + sBOff + i * 16, BH + gBOff + kof + i * 8);
                CPA(stg + OFF_BL + sBOff + i * 16, BL + gBOff + kof + i * 8);
            }
            CPA_COMMIT();
            CPA_WAIT1();
        } else {
            CPA_WAIT0();
        }
        __syncthreads();

        const uint32_t base = sb + (ck & 1) * STGB;
        const uint32_t pAH = base + OFF_AH + aOff, pAL = base + OFF_AL + aOff;
        const uint32_t pBH = base + OFF_BH + bOff, pBL = base + OFF_BL + bOff;
#pragma unroll
        for (int ka = 0; ka < 4; ka++) {
            uint32_t A[4][4], Bh[2][4], Bl[2][4];
#pragma unroll
            for (int m = 0; m < 4; m++) ldsm4(A[m], pAH + m * (16 * SRB) + ka * 32);
#pragma unroll
            for (int nb = 0; nb < 2; nb++) ldsm4(Bh[nb], pBH + nb * (16 * SRB) + ka * 32);
#pragma unroll
            for (int m = 0; m < 4; m++)
#pragma unroll
                for (int n8 = 0; n8 < 4; n8++)
                    mma_bf16(acc[m][n8], A[m], Bh[n8 >> 1][(n8 & 1) * 2], Bh[n8 >> 1][(n8 & 1) * 2 + 1]);
#pragma unroll
            for (int nb = 0; nb < 2; nb++) ldsm4(Bl[nb], pBL + nb * (16 * SRB) + ka * 32);
#pragma unroll
            for (int m = 0; m < 4; m++)
#pragma unroll
                for (int n8 = 0; n8 < 4; n8++)
                    mma_bf16(acc[m][n8], A[m], Bl[n8 >> 1][(n8 & 1) * 2], Bl[n8 >> 1][(n8 & 1) * 2 + 1]);
#pragma unroll
            for (int m = 0; m < 4; m++) ldsm4(A[m], pAL + m * (16 * SRB) + ka * 32);
#pragma unroll
            for (int m = 0; m < 4; m++)
#pragma unroll
                for (int n8 = 0; n8 < 4; n8++)
                    mma_bf16(acc[m][n8], A[m], Bh[n8 >> 1][(n8 & 1) * 2], Bh[n8 >> 1][(n8 & 1) * 2 + 1]);
        }
        __syncthreads();
    }

    // epilogue -> fp16
    const int rBase = wm * 64 + (lane >> 2);
    const int cBase = wn * 32 + (lane & 3) * 2;
    fp16* O = (MODE == 0) ? g_McTf : g_EPf;
    size_t rowB = (MODE == 0) ? (size_t)bz * HH * HH + (size_t)(by * 128) * HH
                              : (size_t)bz * 128 * HH;
#pragma unroll
    for (int m = 0; m < 4; m++) {
        int r0 = m * 16 + rBase;
#pragma unroll
        for (int n8 = 0; n8 < 4; n8++) {
            int cc = bx * 256 + cBase + n8 * 8;
            *(uint32_t*)&O[rowB + (size_t)r0 * HH + cc] = packh(acc[m][n8][0], acc[m][n8][1]);
            *(uint32_t*)&O[rowB + (size_t)(r0 + 8) * HH + cc] = packh(acc[m][n8][2], acc[m][n8][3]);
        }
    }
}

// ------------------------------ fp16 GEMM ---------------------------------
// OM 0: T = hidF . McTf^T            (fp16 out, grid: x=HH/128, y=BB*SS/128, z=CC)
// OM 1: out = ([Tf;EPf].hidF^T)*vsum (fp32 out, grid: x=SS/128, y=17, z=CC*BB)
// CTA tile 128x128, 8 warps (2x4), warp tile 64x32, K-chunk 64, 3-stage,
// 2 CTAs/SM so the two CTAs' ldsm/MMA phases interleave on the SM.
template <int OM>
__global__ void __launch_bounds__(NTF, 2) k_fp16(float* __restrict__ out) {
    extern __shared__ __align__(128) char smem[];
    const uint32_t sb = smem_to_u32(smem);
    const int tid = threadIdx.x, wid = tid >> 5, lane = tid & 31;
    const int bx = blockIdx.x, by = blockIdx.y, bz = blockIdx.z;
    const int c = (OM == 1) ? (bz >> 4) : bz;
    const int b = (OM == 1) ? (bz & 15) : 0;

    const fp16 *Af, *Bf;
    if (OM == 0) {
        Af = g_hidF + (size_t)by * 128 * HH;
        Bf = g_McTf + (size_t)bz * HH * HH + (size_t)bx * 128 * HH;
    } else {
        Af = (by < 16)
            ? g_Tf + ((size_t)c * BB * SS + (size_t)b * SS + (size_t)by * 128) * HH
            : g_EPf + (size_t)c * 128 * HH;
        Bf = g_hidF + ((size_t)b * SS + (size_t)bx * 128) * HH;
    }

    // loaders (256 thr): A and B each 128 rows, 2 thr/row, 64B half each
    const int lrow = tid >> 1, lhalf = tid & 1;
    const uint32_t sLOff = (uint32_t)(lrow * SRB + lhalf * 64);
    const size_t gLOff = (size_t)lrow * HH + lhalf * 32;

    // compute mapping: 8 warps, warp grid 2(m) x 4(n), warp tile 64x32
    const int wm = wid >> 2, wn = wid & 3;
    const uint32_t aOff = (uint32_t)((wm * 64 + (lane & 15)) * SRB + ((lane >> 4) << 4));
    const uint32_t bOff = (uint32_t)(OFF_BF + (wn * 32 + (lane & 7) + ((lane >> 4) & 1) * 8) * SRB +
                                     (((lane >> 3) & 1) << 4));

    float acc[4][4][4] = {};

    // prologue: chunks 0,1 -> stages 0,1
#pragma unroll
    for (int pc = 0; pc < 2; pc++) {
        const uint32_t stg = sb + pc * STG_F;
        const int kof = pc * 64;
#pragma unroll
        for (int i = 0; i < 4; i++) {
            CPA(stg + sLOff + i * 16, Af + gLOff + kof + i * 8);
            CPA(stg + OFF_BF + sLOff + i * 16, Bf + gLOff + kof + i * 8);
        }
        CPA_COMMIT();
    }

    int stage = 0;
    for (int ck = 0; ck < NC; ck++) {
        if (ck + 2 < NC) {
            int s2 = stage + 2; if (s2 >= NSTG_F) s2 -= NSTG_F;
            const uint32_t stg = sb + s2 * STG_F;
            const int kof = (ck + 2) * 64;
#pragma unroll
            for (int i = 0; i < 4; i++) {
                CPA(stg + sLOff + i * 16, Af + gLOff + kof + i * 8);
                CPA(stg + OFF_BF + sLOff + i * 16, Bf + gLOff + kof + i * 8);
            }
            CPA_COMMIT();
            CPA_WAIT2();
        } else if (ck + 1 < NC) {
            CPA_WAIT1();
        } else {
            CPA_WAIT0();
        }
        __syncthreads();

        const uint32_t pA = sb + stage * STG_F + aOff;
        const uint32_t pB = sb + stage * STG_F + bOff;
#pragma unroll
        for (int ka = 0; ka < 4; ka++) {
            uint32_t A[4][4], Bq[2][4];
#pragma unroll
            for (int m = 0; m < 4; m++) ldsm4(A[m], pA + m * (16 * SRB) + ka * 32);
#pragma unroll
            for (int nb = 0; nb < 2; nb++) ldsm4(Bq[nb], pB + nb * (16 * SRB) + ka * 32);
#pragma unroll
            for (int m = 0; m < 4; m++)
#pragma unroll
                for (int n8 = 0; n8 < 4; n8++)
                    mma_fp16(acc[m][n8], A[m],
                             Bq[n8 >> 1][(n8 & 1) * 2], Bq[n8 >> 1][(n8 & 1) * 2 + 1]);
        }
        __syncthreads();
        if (++stage == NSTG_F) stage = 0;
    }

    // ------------------------------ epilogue --------------------------------
    const int rBase = wm * 64 + (lane >> 2);
    const int cBase = wn * 32 + (lane & 3) * 2;
    if (OM == 0) {
        size_t rowB = ((size_t)bz * BB * SS + (size_t)by * 128) * HH;
#pragma unroll
        for (int m = 0; m < 4; m++) {
            int r0 = m * 16 + rBase;
#pragma unroll
            for (int n8 = 0; n8 < 4; n8++) {
                int cc = bx * 128 + cBase + n8 * 8;
                *(uint32_t*)&g_Tf[rowB + (size_t)r0 * HH + cc] = packh(acc[m][n8][0], acc[m][n8][1]);
                *(uint32_t*)&g_Tf[rowB + (size_t)(r0 + 8) * HH + cc] = packh(acc[m][n8][2], acc[m][n8][3]);
            }
        }
    } else {
        const float* vsp = g_vsum + ((size_t)c * BB + b) * SS + bx * 128;
        float* ob = out + ((size_t)b * CC + c) * SF * SS;
#pragma unroll
        for (int m = 0; m < 4; m++) {
            int r0 = by * 128 + m * 16 + rBase;
#pragma unroll
            for (int n8 = 0; n8 < 4; n8++) {
                int cc = cBase + n8 * 8;
                float2 vs = *(const float2*)(vsp + cc);
                size_t col = (size_t)bx * 128 + cc;
                if (r0 < SF) {
                    float2 o;
                    o.x = acc[m][n8][0] * vs.x;
                    o.y = acc[m][n8][1] * vs.y;
                    *(float2*)(ob + (size_t)r0 * SS + col) = o;
                }
                if (r0 + 8 < SF) {
                    float2 o;
                    o.x = acc[m][n8][2] * vs.x;
                    o.y = acc[m][n8][3] * vs.y;
                    *(float2*)(ob + (size_t)(r0 + 8) * SS + col) = o;
                }
            }
        }
    }
}

// ------------------------------ launch ------------------------------------
extern "C" void kernel_launch(void* const* d_in, const int* in_sizes, int n_in,
                              void* d_out, int out_size) {
    const float* hidden = (const float*)d_in[0];
    const float* emb    = (const float*)d_in[1];
    const float* Wk     = (const float*)d_in[2];
    const float* Wq     = (const float*)d_in[3];
    const float* Wv     = (const float*)d_in[4];
    float* out = (float*)d_out;

    cudaFuncSetAttribute(k_gemm<0>, cudaFuncAttributeMaxDynamicSharedMemorySize, SMEM_G);
    cudaFuncSetAttribute(k_gemm<1>, cudaFuncAttributeMaxDynamicSharedMemorySize, SMEM_G);
    cudaFuncSetAttribute(k_fp16<0>, cudaFuncAttributeMaxDynamicSharedMemorySize, SMEM_F);
    cudaFuncSetAttribute(k_fp16<1>, cudaFuncAttributeMaxDynamicSharedMemorySize, SMEM_F);

    // launch order chosen so the 4th launch (ncu capture slot) is k_fp16<0> (T)
    k_cvt<<<HID_BLOCKS + 64, 256>>>(hidden, emb);                  // 1
    k_tsplit_both<<<dim3(32, 32, 2 * CC), dim3(32, 8)>>>(Wq, Wk);  // 2
    k_gemm<0><<<dim3(4, 8, CC), NT, SMEM_G>>>();                   // 3: McT
    k_fp16<0><<<dim3(8, 256, CC), NTF, SMEM_F>>>(nullptr);         // 4: T  <- ncu
    k_gemm<1><<<dim3(4, 1, CC), NT, SMEM_G>>>();                   // 5: E
    k_wvsum<<<dim3(HH / 256, CC), 256>>>(Wv);                      // 6
    k_vsum<<<(BB * SS) / 8, 256>>>(hidden);                        // 7
    k_fp16<1><<<dim3(16, 17, CC * BB), NTF, SMEM_F>>>(out);        // 8: scores
}

// round 16
// speedup vs baseline: 1.1494x; 1.0284x over previous
#include <cuda_runtime.h>
#include <cuda_bf16.h>
#include <cuda_fp16.h>
#include <cstdint>

#define CC 2
#define FF 32
#define HH 1024
#define BB 16
#define SS 2048
#define SF (SS + FF)   // 2080
#define NC 16          // K chunks of 64
#define SRB 144        // smem row bytes (128 data + 16 pad)
// 3-split bf16 GEMM staging: Ahi,Alo,Bhi,Blo (tile 128x256)
#define OFF_AH 0
#define OFF_AL (128 * SRB)
#define OFF_BH (256 * SRB)
#define OFF_BL (512 * SRB)
#define STGB (768 * SRB)            // 110592
#define SMEM_G (2 * STGB)           // 221184
#define NT 512
// fp16 GEMM staging (tile 128x128): A 128 rows + B 128 rows, 3 stages, 2 CTAs/SM
#define OFF_BF (128 * SRB)
#define STG_F (256 * SRB)           // 36864
#define NSTG_F 3
#define SMEM_F (NSTG_F * STG_F)     // 110592
#define NTF 256

typedef __nv_bfloat16 bf16;
typedef __half fp16;

// ------------------------------ device scratch ----------------------------
__device__ fp16 g_hidF[(size_t)BB * SS * HH];
__device__ bf16 g_WqTH[(size_t)CC * HH * HH], g_WqTL[(size_t)CC * HH * HH];
__device__ bf16 g_WkTH[(size_t)CC * HH * HH], g_WkTL[(size_t)CC * HH * HH];
__device__ fp16 g_McTf[(size_t)CC * HH * HH];
__device__ bf16 g_embPH[(size_t)CC * 128 * HH], g_embPL[(size_t)CC * 128 * HH];  // rows>=32 stay 0
__device__ fp16 g_EPf[(size_t)CC * 128 * HH];
__device__ fp16 g_Tf[(size_t)CC * BB * SS * HH];
__device__ float g_wvs[CC * HH];
__device__ float g_vsum[(size_t)CC * BB * SS];

// ------------------------------ helpers -----------------------------------
__device__ __forceinline__ uint32_t smem_to_u32(const void* p) {
    uint32_t a;
    asm("{ .reg .u64 t; cvta.to.shared.u64 t, %1; cvt.u32.u64 %0, t; }" : "=r"(a) : "l"(p));
    return a;
}
__device__ __forceinline__ void split2(float x, bf16& h, bf16& l) {
    h = __float2bfloat16(x);
    l = __float2bfloat16(x - __bfloat162float(h));
}
__device__ __forceinline__ uint32_t packbf(bf16 a, bf16 b) {
    return (uint32_t)__bfloat16_as_ushort(a) | ((uint32_t)__bfloat16_as_ushort(b) << 16);
}
__device__ __forceinline__ uint32_t packh(float a, float b) {
    __half2 h = __floats2half2_rn(a, b);
    return *(uint32_t*)&h;
}
__device__ __forceinline__ void ldsm4(uint32_t* r, uint32_t addr) {
    asm volatile("ldmatrix.sync.aligned.m8n8.x4.shared.b16 {%0,%1,%2,%3}, [%4];"
                 : "=r"(r[0]), "=r"(r[1]), "=r"(r[2]), "=r"(r[3]) : "r"(addr));
}
__device__ __forceinline__ void mma_bf16(float* c, const uint32_t* a, uint32_t b0, uint32_t b1) {
    asm volatile(
        "mma.sync.aligned.m16n8k16.row.col.f32.bf16.bf16.f32 "
        "{%0,%1,%2,%3},{%4,%5,%6,%7},{%8,%9},{%0,%1,%2,%3};"
        : "+f"(c[0]), "+f"(c[1]), "+f"(c[2]), "+f"(c[3])
        : "r"(a[0]), "r"(a[1]), "r"(a[2]), "r"(a[3]), "r"(b0), "r"(b1));
}
__device__ __forceinline__ void mma_fp16(float* c, const uint32_t* a, uint32_t b0, uint32_t b1) {
    asm volatile(
        "mma.sync.aligned.m16n8k16.row.col.f32.f16.f16.f32 "
        "{%0,%1,%2,%3},{%4,%5,%6,%7},{%8,%9},{%0,%1,%2,%3};"
        : "+f"(c[0]), "+f"(c[1]), "+f"(c[2]), "+f"(c[3])
        : "r"(a[0]), "r"(a[1]), "r"(a[2]), "r"(a[3]), "r"(b0), "r"(b1));
}
#define CPA(s, g) asm volatile("cp.async.cg.shared.global [%0], [%1], 16;" :: "r"(s), "l"(g))
#define CPA_COMMIT() asm volatile("cp.async.commit_group;" ::: "memory")
#define CPA_WAIT1() asm volatile("cp.async.wait_group 1;" ::: "memory")
#define CPA_WAIT0() asm volatile("cp.async.wait_group 0;" ::: "memory")

// ------------------------------ prep kernels ------------------------------
__global__ void k_wvsum(const float* __restrict__ Wv) {
    int c = blockIdx.y;
    int h = blockIdx.x * 256 + threadIdx.x;
    const float* W = Wv + (size_t)c * HH * HH;
    float a = 0.f;
#pragma unroll 8
    for (int o = 0; o < HH; ++o) a += W[(size_t)o * HH + h];
    g_wvs[c * HH + h] = a;
}

// fused: hidden -> fp16 conversion + vsum (one pass), plus emb hi/lo split
#define CVT_HID_BLOCKS 8192   // each handles 4 rows of H=1024
__global__ void k_cvt(const float* __restrict__ hidden, const float* __restrict__ emb) {
    int bid = blockIdx.x;
    if (bid < CVT_HID_BLOCKS) {
        __shared__ float wv0[HH], wv1[HH];
        __shared__ float rsum[4][2];
        const int tid = threadIdx.x;
        for (int i = tid; i < HH; i += 256) {
            wv0[i] = g_wvs[i];
            wv1[i] = g_wvs[HH + i];
        }
        if (tid < 8) rsum[tid >> 1][tid & 1] = 0.f;
        __syncthreads();
        const int w = tid >> 5, lane = tid & 31;
        const int row = w >> 1;                       // 0..3 within block
        const size_t grow = (size_t)bid * 4 + row;    // global (b,s) row
        const float4* src = (const float4*)(hidden + grow * HH);
        uint32_t* dstF = (uint32_t*)(g_hidF + grow * HH);
        const int base = (w & 1) * 128 + lane * 4;    // float4 index in row
        float a0 = 0.f, a1 = 0.f;
#pragma unroll
        for (int j = 0; j < 4; j++) {
            int f4 = base + j;
            float4 v = src[f4];
            dstF[2 * f4] = packh(v.x, v.y);
            dstF[2 * f4 + 1] = packh(v.z, v.w);
            int i0 = f4 * 4;
            a0 += v.x * wv0[i0] + v.y * wv0[i0 + 1] + v.z * wv0[i0 + 2] + v.w * wv0[i0 + 3];
            a1 += v.x * wv1[i0] + v.y * wv1[i0 + 1] + v.z * wv1[i0 + 2] + v.w * wv1[i0 + 3];
        }
#pragma unroll
        for (int off = 16; off; off >>= 1) {
            a0 += __shfl_down_sync(0xFFFFFFFFu, a0, off);
            a1 += __shfl_down_sync(0xFFFFFFFFu, a1, off);
        }
        if (lane == 0) {
            atomicAdd(&rsum[row][0], a0);
            atomicAdd(&rsum[row][1], a1);
        }
        __syncthreads();
        if (tid < 8) {
            int r = tid >> 1, ch = tid & 1;
            size_t g2 = (size_t)bid * 4 + r;
            if (ch == 0) g_vsum[g2] = rsum[r][0];
            else g_vsum[(size_t)BB * SS + g2] = rsum[r][1];
        }
    } else {
        int i = (bid - CVT_HID_BLOCKS) * 256 + threadIdx.x;
        int e = i * 4;
        int c = e / (FF * HH);
        int rem = e - c * FF * HH;
        int f = rem / HH, h = rem - f * HH;
        float4 v = ((const float4*)emb)[i];
        bf16 h0, l0, h1, l1, h2, l2, h3, l3;
        split2(v.x, h0, l0); split2(v.y, h1, l1); split2(v.z, h2, l2); split2(v.w, h3, l3);
        size_t o = ((size_t)c * 128 + f) * HH + h;
        *(uint32_t*)&g_embPH[o] = packbf(h0, h1);
        *(uint32_t*)&g_embPH[o + 2] = packbf(h2, h3);
        *(uint32_t*)&g_embPL[o] = packbf(l0, l1);
        *(uint32_t*)&g_embPL[o + 2] = packbf(l2, l3);
    }
}

__global__ void k_tsplit_both(const float* __restrict__ Wq, const float* __restrict__ Wk) {
    __shared__ float t[32][33];
    int z = blockIdx.z;
    int c = z >> 1, W = z & 1;
    const float* I = (W == 0 ? Wq : Wk) + (size_t)c * HH * HH;
    bf16* OH = (W == 0 ? g_WqTH : g_WkTH) + (size_t)c * HH * HH;
    bf16* OL = (W == 0 ? g_WqTL : g_WkTL) + (size_t)c * HH * HH;
    int x = blockIdx.x * 32 + threadIdx.x;
#pragma unroll
    for (int i = threadIdx.y; i < 32; i += 8)
        t[i][threadIdx.x] = I[(size_t)(blockIdx.y * 32 + i) * HH + x];
    __syncthreads();
    int ox = blockIdx.y * 32 + threadIdx.x;
#pragma unroll
    for (int i = threadIdx.y; i < 32; i += 8) {
        float v = t[threadIdx.x][i];
        bf16 h, l;
        split2(v, h, l);
        size_t o = (size_t)(blockIdx.x * 32 + i) * HH + ox;
        OH[o] = h;
        OL[o] = l;
    }
}

// ------------------------------ 3-split bf16 GEMM (modes 0-1) -------------
// C[128,256] = (Ahi+Alo).(Bhi+Blo)^T, 16 warps, warp tile 64x32, 2-stage.
// MODE 0: McT (fp16 out)   1: E (fp16 out)
template <int MODE>
__global__ void __launch_bounds__(NT, 1) k_gemm() {
    extern __shared__ __align__(128) char smem[];
    const uint32_t sb = smem_to_u32(smem);
    const int tid = threadIdx.x, wid = tid >> 5, lane = tid & 31;
    const int bx = blockIdx.x, by = blockIdx.y, bz = blockIdx.z;

    const bf16 *AH, *AL, *BH, *BL;
    if (MODE == 0) {
        size_t cb = (size_t)bz * HH * HH;
        AH = g_WkTH + cb + (size_t)by * 128 * HH; AL = g_WkTL + cb + (size_t)by * 128 * HH;
        BH = g_WqTH + cb + (size_t)bx * 256 * HH; BL = g_WqTL + cb + (size_t)bx * 256 * HH;
    } else {
        AH = g_embPH + (size_t)bz * 128 * HH; AL = g_embPL + (size_t)bz * 128 * HH;
        size_t cb = (size_t)bz * HH * HH;
        BH = g_WkTH + cb + (size_t)bx * 256 * HH; BL = g_WkTL + cb + (size_t)bx * 256 * HH;
    }

    const int arow = tid >> 2, aq = tid & 3;
    const uint32_t sAOff = (uint32_t)(arow * SRB + aq * 32);
    const size_t gAOff = (size_t)arow * HH + aq * 16;
    const int brow = tid >> 1, bhalf = tid & 1;
    const uint32_t sBOff = (uint32_t)(brow * SRB + bhalf * 64);
    const size_t gBOff = (size_t)brow * HH + bhalf * 32;

    const int wm = wid >> 3, wn = wid & 7;
    const uint32_t aOff = (uint32_t)((wm * 64 + (lane & 15)) * SRB + ((lane >> 4) << 4));
    const uint32_t bOff = (uint32_t)((wn * 32 + (lane & 7) + ((lane >> 4) & 1) * 8) * SRB +
                                     (((lane >> 3) & 1) << 4));

    float acc[4][4][4] = {};

    {
#pragma unroll
        for (int i = 0; i < 2; i++) {
            CPA(sb + OFF_AH + sAOff + i * 16, AH + gAOff + i * 8);
            CPA(sb + OFF_AL + sAOff + i * 16, AL + gAOff + i * 8);
        }
#pragma unroll
        for (int i = 0; i < 4; i++) {
            CPA(sb + OFF_BH + sBOff + i * 16, BH + gBOff + i * 8);
            CPA(sb + OFF_BL + sBOff + i * 16, BL + gBOff + i * 8);
        }
        CPA_COMMIT();
    }

    for (int ck = 0; ck < NC; ck++) {
        if (ck + 1 < NC) {
            const uint32_t stg = sb + ((ck + 1) & 1) * STGB;
            const int kof = (ck + 1) * 64;
#pragma unroll
            for (int i = 0; i < 2; i++) {
                CPA(stg + OFF_AH + sAOff + i * 16, AH + gAOff + kof + i * 8);
                CPA(stg + OFF_AL + sAOff + i * 16, AL + gAOff + kof + i * 8);
            }
#pragma unroll
            for (int i = 0; i < 4; i++) {
                CPA(stg + OFF_BH + sBOff + i * 16, BH + gBOff + kof + i * 8);
                CPA(stg + OFF_BL + sBOff + i * 16, BL + gBOff + kof + i * 8);
            }
            CPA_COMMIT();
            CPA_WAIT1();
        } else {
            CPA_WAIT0();
        }
        __syncthreads();

        const uint32_t base = sb + (ck & 1) * STGB;
        const uint32_t pAH = base + OFF_AH + aOff, pAL = base + OFF_AL + aOff;
        const uint32_t pBH = base + OFF_BH + bOff, pBL = base + OFF_BL + bOff;
#pragma unroll
        for (int ka = 0; ka < 4; ka++) {
            uint32_t A[4][4], Bh[2][4], Bl[2][4];
#pragma unroll
            for (int m = 0; m < 4; m++) ldsm4(A[m], pAH + m * (16 * SRB) + ka * 32);
#pragma unroll
            for (int nb = 0; nb < 2; nb++) ldsm4(Bh[nb], pBH + nb * (16 * SRB) + ka * 32);
#pragma unroll
            for (int m = 0; m < 4; m++)
#pragma unroll
                for (int n8 = 0; n8 < 4; n8++)
                    mma_bf16(acc[m][n8], A[m], Bh[n8 >> 1][(n8 & 1) * 2], Bh[n8 >> 1][(n8 & 1) * 2 + 1]);
#pragma unroll
            for (int nb = 0; nb < 2; nb++) ldsm4(Bl[nb], pBL + nb * (16 * SRB) + ka * 32);
#pragma unroll
            for (int m = 0; m < 4; m++)
#pragma unroll
                for (int n8 = 0; n8 < 4; n8++)
                    mma_bf16(acc[m][n8], A[m], Bl[n8 >> 1][(n8 & 1) * 2], Bl[n8 >> 1][(n8 & 1) * 2 + 1]);
#pragma unroll
            for (int m = 0; m < 4; m++) ldsm4(A[m], pAL + m * (16 * SRB) + ka * 32);
#pragma unroll
            for (int m = 0; m < 4; m++)
#pragma unroll
                for (int n8 = 0; n8 < 4; n8++)
                    mma_bf16(acc[m][n8], A[m], Bh[n8 >> 1][(n8 & 1) * 2], Bh[n8 >> 1][(n8 & 1) * 2 + 1]);
        }
        __syncthreads();
    }

    // epilogue -> fp16
    const int rBase = wm * 64 + (lane >> 2);
    const int cBase = wn * 32 + (lane & 3) * 2;
    fp16* O = (MODE == 0) ? g_McTf : g_EPf;
    size_t rowB = (MODE == 0) ? (size_t)bz * HH * HH + (size_t)(by * 128) * HH
                              : (size_t)bz * 128 * HH;
#pragma unroll
    for (int m = 0; m < 4; m++) {
        int r0 = m * 16 + rBase;
#pragma unroll
        for (int n8 = 0; n8 < 4; n8++) {
            int cc = bx * 256 + cBase + n8 * 8;
            *(uint32_t*)&O[rowB + (size_t)r0 * HH + cc] = packh(acc[m][n8][0], acc[m][n8][1]);
            *(uint32_t*)&O[rowB + (size_t)(r0 + 8) * HH + cc] = packh(acc[m][n8][2], acc[m][n8][3]);
        }
    }
}

// ------------------------------ fp16 GEMM ---------------------------------
// OM 0: T = hidF . McTf^T            (fp16 out, grid: x=HH/128, y=BB*SS/128, z=CC)
// OM 1: out = ([Tf;EPf].hidF^T)*vsum (fp32 out, grid: x=SS/128, y=17, z=CC*BB)
// CTA tile 128x128, 8 warps (2x4), warp tile 64x32, K-chunk 64, 3-stage,
// 2 CTAs/SM. Single __syncthreads per chunk (issue moved after head sync);
// B fragments double-buffered across ka.
template <int OM>
__global__ void __launch_bounds__(NTF, 2) k_fp16(float* __restrict__ out) {
    extern __shared__ __align__(128) char smem[];
    const uint32_t sb = smem_to_u32(smem);
    const int tid = threadIdx.x, wid = tid >> 5, lane = tid & 31;
    const int bx = blockIdx.x, by = blockIdx.y, bz = blockIdx.z;
    const int c = (OM == 1) ? (bz >> 4) : bz;
    const int b = (OM == 1) ? (bz & 15) : 0;

    const fp16 *Af, *Bf;
    if (OM == 0) {
        Af = g_hidF + (size_t)by * 128 * HH;
        Bf = g_McTf + (size_t)bz * HH * HH + (size_t)bx * 128 * HH;
    } else {
        Af = (by < 16)
            ? g_Tf + ((size_t)c * BB * SS + (size_t)b * SS + (size_t)by * 128) * HH
            : g_EPf + (size_t)c * 128 * HH;
        Bf = g_hidF + ((size_t)b * SS + (size_t)bx * 128) * HH;
    }

    // loaders (256 thr): A and B each 128 rows, 2 thr/row, 64B half each
    const int lrow = tid >> 1, lhalf = tid & 1;
    const uint32_t sLOff = (uint32_t)(lrow * SRB + lhalf * 64);
    const size_t gLOff = (size_t)lrow * HH + lhalf * 32;

    // compute mapping: 8 warps, warp grid 2(m) x 4(n), warp tile 64x32
    const int wm = wid >> 2, wn = wid & 3;
    const uint32_t aOff = (uint32_t)((wm * 64 + (lane & 15)) * SRB + ((lane >> 4) << 4));
    const uint32_t bOff = (uint32_t)(OFF_BF + (wn * 32 + (lane & 7) + ((lane >> 4) & 1) * 8) * SRB +
                                     (((lane >> 3) & 1) << 4));

    float acc[4][4][4] = {};

    // prologue: chunks 0,1 -> stages 0,1
#pragma unroll
    for (int pc = 0; pc < 2; pc++) {
        const uint32_t stg = sb + pc * STG_F;
        const int kof = pc * 64;
#pragma unroll
        for (int i = 0; i < 4; i++) {
            CPA(stg + sLOff + i * 16, Af + gLOff + kof + i * 8);
            CPA(stg + OFF_BF + sLOff + i * 16, Bf + gLOff + kof + i * 8);
        }
        CPA_COMMIT();
    }

    int stage = 0;
    for (int ck = 0; ck < NC; ck++) {
        // wait for chunk ck's data (pending groups: ck, ck+1)
        if (ck + 1 < NC) CPA_WAIT1(); else CPA_WAIT0();
        __syncthreads();  // all warps done with stage s2 (read at ck-1) and see ck's data

        // issue chunk ck+2 into the stage freed by chunk ck-1
        if (ck + 2 < NC) {
            int s2 = stage + 2; if (s2 >= NSTG_F) s2 -= NSTG_F;
            const uint32_t stg = sb + s2 * STG_F;
            const int kof = (ck + 2) * 64;
#pragma unroll
            for (int i = 0; i < 4; i++) {
                CPA(stg + sLOff + i * 16, Af + gLOff + kof + i * 8);
                CPA(stg + OFF_BF + sLOff + i * 16, Bf + gLOff + kof + i * 8);
            }
            CPA_COMMIT();
        }

        const uint32_t pA = sb + stage * STG_F + aOff;
        const uint32_t pB = sb + stage * STG_F + bOff;

        uint32_t Bq[2][2][4];
#pragma unroll
        for (int nb = 0; nb < 2; nb++) ldsm4(Bq[0][nb], pB + nb * (16 * SRB));
#pragma unroll
        for (int ka = 0; ka < 4; ka++) {
            const int cur = ka & 1, nxt = cur ^ 1;
            if (ka < 3) {  // prefetch next-ka B fragments
                const uint32_t ko = (ka + 1) * 32;
#pragma unroll
                for (int nb = 0; nb < 2; nb++) ldsm4(Bq[nxt][nb], pB + nb * (16 * SRB) + ko);
            }
            uint32_t A[4][4];
#pragma unroll
            for (int m = 0; m < 4; m++) ldsm4(A[m], pA + m * (16 * SRB) + ka * 32);
#pragma unroll
            for (int m = 0; m < 4; m++)
#pragma unroll
                for (int n8 = 0; n8 < 4; n8++)
                    mma_fp16(acc[m][n8], A[m],
                             Bq[cur][n8 >> 1][(n8 & 1) * 2], Bq[cur][n8 >> 1][(n8 & 1) * 2 + 1]);
        }
        if (++stage == NSTG_F) stage = 0;
    }

    // ------------------------------ epilogue --------------------------------
    const int rBase = wm * 64 + (lane >> 2);
    const int cBase = wn * 32 + (lane & 3) * 2;
    if (OM == 0) {
        size_t rowB = ((size_t)bz * BB * SS + (size_t)by * 128) * HH;
#pragma unroll
        for (int m = 0; m < 4; m++) {
            int r0 = m * 16 + rBase;
#pragma unroll
            for (int n8 = 0; n8 < 4; n8++) {
                int cc = bx * 128 + cBase + n8 * 8;
                *(uint32_t*)&g_Tf[rowB + (size_t)r0 * HH + cc] = packh(acc[m][n8][0], acc[m][n8][1]);
                *(uint32_t*)&g_Tf[rowB + (size_t)(r0 + 8) * HH + cc] = packh(acc[m][n8][2], acc[m][n8][3]);
            }
        }
    } else {
        const float* vsp = g_vsum + ((size_t)c * BB + b) * SS + bx * 128;
        float* ob = out + ((size_t)b * CC + c) * SF * SS;
#pragma unroll
        for (int m = 0; m < 4; m++) {
            int r0 = by * 128 + m * 16 + rBase;
#pragma unroll
            for (int n8 = 0; n8 < 4; n8++) {
                int cc = cBase + n8 * 8;
                float2 vs = *(const float2*)(vsp + cc);
                size_t col = (size_t)bx * 128 + cc;
                if (r0 < SF) {
                    float2 o;
                    o.x = acc[m][n8][0] * vs.x;
                    o.y = acc[m][n8][1] * vs.y;
                    *(float2*)(ob + (size_t)r0 * SS + col) = o;
                }
                if (r0 + 8 < SF) {
                    float2 o;
                    o.x = acc[m][n8][2] * vs.x;
                    o.y = acc[m][n8][3] * vs.y;
                    *(float2*)(ob + (size_t)(r0 + 8) * SS + col) = o;
                }
            }
        }
    }
}

// ------------------------------ launch ------------------------------------
extern "C" void kernel_launch(void* const* d_in, const int* in_sizes, int n_in,
                              void* d_out, int out_size) {
    const float* hidden = (const float*)d_in[0];
    const float* emb    = (const float*)d_in[1];
    const float* Wk     = (const float*)d_in[2];
    const float* Wq     = (const float*)d_in[3];
    const float* Wv     = (const float*)d_in[4];
    float* out = (float*)d_out;

    cudaFuncSetAttribute(k_gemm<0>, cudaFuncAttributeMaxDynamicSharedMemorySize, SMEM_G);
    cudaFuncSetAttribute(k_gemm<1>, cudaFuncAttributeMaxDynamicSharedMemorySize, SMEM_G);
    cudaFuncSetAttribute(k_fp16<0>, cudaFuncAttributeMaxDynamicSharedMemorySize, SMEM_F);
    cudaFuncSetAttribute(k_fp16<1>, cudaFuncAttributeMaxDynamicSharedMemorySize, SMEM_F);

    k_wvsum<<<dim3(HH / 256, CC), 256>>>(Wv);                      // 1
    k_cvt<<<CVT_HID_BLOCKS + 64, 256>>>(hidden, emb);              // 2 (hidF + vsum + emb)
    k_tsplit_both<<<dim3(32, 32, 2 * CC), dim3(32, 8)>>>(Wq, Wk);  // 3
    k_gemm<0><<<dim3(4, 8, CC), NT, SMEM_G>>>();                   // 4: McT <- ncu
    k_fp16<0><<<dim3(8, 256, CC), NTF, SMEM_F>>>(nullptr);         // 5: T
    k_gemm<1><<<dim3(4, 1, CC), NT, SMEM_G>>>();                   // 6: E
    k_fp16<1><<<dim3(16, 17, CC * BB), NTF, SMEM_F>>>(out);        // 7: scores
}

// round 17
// speedup vs baseline: 1.2115x; 1.0540x over previous
#include <cuda_runtime.h>
#include <cuda_bf16.h>
#include <cuda_fp16.h>
#include <cstdint>

#define CC 2
#define FF 32
#define HH 1024
#define BB 16
#define SS 2048
#define SF (SS + FF)   // 2080
#define NC 16          // K chunks of 64
#define NCH 8          // split-K half
#define SRB 144        // smem row bytes (128 data + 16 pad)
// 3-split bf16 GEMM staging: Ahi,Alo,Bhi,Blo (tile 128x256)
#define OFF_AH 0
#define OFF_AL (128 * SRB)
#define OFF_BH (256 * SRB)
#define OFF_BL (512 * SRB)
#define STGB (768 * SRB)            // 110592
#define SMEM_G (2 * STGB)           // 221184
#define NT 512
// fp16 GEMM staging (tile 128x128): A 128 rows + B 128 rows, 3 stages, 2 CTAs/SM
#define OFF_BF (128 * SRB)
#define STG_F (256 * SRB)           // 36864
#define NSTG_F 3
#define SMEM_F (NSTG_F * STG_F)     // 110592
#define NTF 256
#define MCN ((size_t)CC * HH * HH)  // Mc element count

typedef __nv_bfloat16 bf16;
typedef __half fp16;

// ------------------------------ device scratch ----------------------------
__device__ fp16 g_hidF[(size_t)BB * SS * HH];
__device__ bf16 g_WqTH[(size_t)CC * HH * HH], g_WqTL[(size_t)CC * HH * HH];
__device__ bf16 g_WkTH[(size_t)CC * HH * HH], g_WkTL[(size_t)CC * HH * HH];
__device__ fp16 g_WkTf[(size_t)CC * HH * HH];
__device__ float g_McP[2 * MCN];                 // split-K fp32 partials
__device__ fp16 g_McTf[MCN];
__device__ fp16 g_embF[(size_t)CC * 128 * HH];   // rows>=32 stay 0 (static zero-init)
__device__ fp16 g_EPf[(size_t)CC * 128 * HH];
__device__ fp16 g_Tf[(size_t)CC * BB * SS * HH];
__device__ float g_wvs[CC * HH];
__device__ float g_vsum[(size_t)CC * BB * SS];

// ------------------------------ helpers -----------------------------------
__device__ __forceinline__ uint32_t smem_to_u32(const void* p) {
    uint32_t a;
    asm("{ .reg .u64 t; cvta.to.shared.u64 t, %1; cvt.u32.u64 %0, t; }" : "=r"(a) : "l"(p));
    return a;
}
__device__ __forceinline__ void split2(float x, bf16& h, bf16& l) {
    h = __float2bfloat16(x);
    l = __float2bfloat16(x - __bfloat162float(h));
}
__device__ __forceinline__ uint32_t packh(float a, float b) {
    __half2 h = __floats2half2_rn(a, b);
    return *(uint32_t*)&h;
}
__device__ __forceinline__ void ldsm4(uint32_t* r, uint32_t addr) {
    asm volatile("ldmatrix.sync.aligned.m8n8.x4.shared.b16 {%0,%1,%2,%3}, [%4];"
                 : "=r"(r[0]), "=r"(r[1]), "=r"(r[2]), "=r"(r[3]) : "r"(addr));
}
__device__ __forceinline__ void mma_bf16(float* c, const uint32_t* a, uint32_t b0, uint32_t b1) {
    asm volatile(
        "mma.sync.aligned.m16n8k16.row.col.f32.bf16.bf16.f32 "
        "{%0,%1,%2,%3},{%4,%5,%6,%7},{%8,%9},{%0,%1,%2,%3};"
        : "+f"(c[0]), "+f"(c[1]), "+f"(c[2]), "+f"(c[3])
        : "r"(a[0]), "r"(a[1]), "r"(a[2]), "r"(a[3]), "r"(b0), "r"(b1));
}
__device__ __forceinline__ void mma_fp16(float* c, const uint32_t* a, uint32_t b0, uint32_t b1) {
    asm volatile(
        "mma.sync.aligned.m16n8k16.row.col.f32.f16.f16.f32 "
        "{%0,%1,%2,%3},{%4,%5,%6,%7},{%8,%9},{%0,%1,%2,%3};"
        : "+f"(c[0]), "+f"(c[1]), "+f"(c[2]), "+f"(c[3])
        : "r"(a[0]), "r"(a[1]), "r"(a[2]), "r"(a[3]), "r"(b0), "r"(b1));
}
#define CPA(s, g) asm volatile("cp.async.cg.shared.global [%0], [%1], 16;" :: "r"(s), "l"(g))
#define CPA_COMMIT() asm volatile("cp.async.commit_group;" ::: "memory")
#define CPA_WAIT1() asm volatile("cp.async.wait_group 1;" ::: "memory")
#define CPA_WAIT0() asm volatile("cp.async.wait_group 0;" ::: "memory")

// ------------------------------ prep kernels ------------------------------
__global__ void k_wvsum(const float* __restrict__ Wv) {
    int c = blockIdx.y;
    int h = blockIdx.x * 256 + threadIdx.x;
    const float* W = Wv + (size_t)c * HH * HH;
    float a = 0.f;
#pragma unroll 8
    for (int o = 0; o < HH; ++o) a += W[(size_t)o * HH + h];
    g_wvs[c * HH + h] = a;
}

// fused: hidden -> fp16 + vsum (one pass); emb -> fp16 (padded)
#define CVT_HID_BLOCKS 8192   // each handles 4 rows of H=1024
__global__ void k_cvt(const float* __restrict__ hidden, const float* __restrict__ emb) {
    int bid = blockIdx.x;
    if (bid < CVT_HID_BLOCKS) {
        __shared__ float wv0[HH], wv1[HH];
        __shared__ float rsum[4][2];
        const int tid = threadIdx.x;
        for (int i = tid; i < HH; i += 256) {
            wv0[i] = g_wvs[i];
            wv1[i] = g_wvs[HH + i];
        }
        if (tid < 8) rsum[tid >> 1][tid & 1] = 0.f;
        __syncthreads();
        const int w = tid >> 5, lane = tid & 31;
        const int row = w >> 1;
        const size_t grow = (size_t)bid * 4 + row;
        const float4* src = (const float4*)(hidden + grow * HH);
        uint32_t* dstF = (uint32_t*)(g_hidF + grow * HH);
        const int base = (w & 1) * 128 + lane * 4;
        float a0 = 0.f, a1 = 0.f;
#pragma unroll
        for (int j = 0; j < 4; j++) {
            int f4 = base + j;
            float4 v = src[f4];
            dstF[2 * f4] = packh(v.x, v.y);
            dstF[2 * f4 + 1] = packh(v.z, v.w);
            int i0 = f4 * 4;
            a0 += v.x * wv0[i0] + v.y * wv0[i0 + 1] + v.z * wv0[i0 + 2] + v.w * wv0[i0 + 3];
            a1 += v.x * wv1[i0] + v.y * wv1[i0 + 1] + v.z * wv1[i0 + 2] + v.w * wv1[i0 + 3];
        }
#pragma unroll
        for (int off = 16; off; off >>= 1) {
            a0 += __shfl_down_sync(0xFFFFFFFFu, a0, off);
            a1 += __shfl_down_sync(0xFFFFFFFFu, a1, off);
        }
        if (lane == 0) {
            atomicAdd(&rsum[row][0], a0);
            atomicAdd(&rsum[row][1], a1);
        }
        __syncthreads();
        if (tid < 8) {
            int r = tid >> 1, ch = tid & 1;
            size_t g2 = (size_t)bid * 4 + r;
            if (ch == 0) g_vsum[g2] = rsum[r][0];
            else g_vsum[(size_t)BB * SS + g2] = rsum[r][1];
        }
    } else {
        int i = (bid - CVT_HID_BLOCKS) * 256 + threadIdx.x;  // float4 idx, 16384 total
        int e = i * 4;
        int c = e / (FF * HH);
        int rem = e - c * FF * HH;
        int f = rem / HH, h = rem - f * HH;
        float4 v = ((const float4*)emb)[i];
        size_t o = ((size_t)c * 128 + f) * HH + h;
        *(uint32_t*)&g_embF[o] = packh(v.x, v.y);
        *(uint32_t*)&g_embF[o + 2] = packh(v.z, v.w);
    }
}

__global__ void k_tsplit_both(const float* __restrict__ Wq, const float* __restrict__ Wk) {
    __shared__ float t[32][33];
    int z = blockIdx.z;
    int c = z >> 1, W = z & 1;
    const float* I = (W == 0 ? Wq : Wk) + (size_t)c * HH * HH;
    bf16* OH = (W == 0 ? g_WqTH : g_WkTH) + (size_t)c * HH * HH;
    bf16* OL = (W == 0 ? g_WqTL : g_WkTL) + (size_t)c * HH * HH;
    fp16* OF = g_WkTf + (size_t)c * HH * HH;
    int x = blockIdx.x * 32 + threadIdx.x;
#pragma unroll
    for (int i = threadIdx.y; i < 32; i += 8)
        t[i][threadIdx.x] = I[(size_t)(blockIdx.y * 32 + i) * HH + x];
    __syncthreads();
    int ox = blockIdx.y * 32 + threadIdx.x;
#pragma unroll
    for (int i = threadIdx.y; i < 32; i += 8) {
        float v = t[threadIdx.x][i];
        bf16 h, l;
        split2(v, h, l);
        size_t o = (size_t)(blockIdx.x * 32 + i) * HH + ox;
        OH[o] = h;
        OL[o] = l;
        if (W == 1) OF[o] = __float2half(v);
    }
}

// ------------------------------ 3-split bf16 GEMM: McT (split-K=2) --------
// grid (4, 8, CC*2): c = bz>>1, kh = bz&1 covers K chunks [kh*8, kh*8+8).
// Writes fp32 partials to g_McP[kh].
__global__ void __launch_bounds__(NT, 1) k_gemm() {
    extern __shared__ __align__(128) char smem[];
    const uint32_t sb = smem_to_u32(smem);
    const int tid = threadIdx.x, wid = tid >> 5, lane = tid & 31;
    const int bx = blockIdx.x, by = blockIdx.y;
    const int c = blockIdx.z >> 1, kh = blockIdx.z & 1;
    const int KB = kh * (NCH * 64);   // element offset of this half's K range

    size_t cb = (size_t)c * HH * HH;
    const bf16* AH = g_WkTH + cb + (size_t)by * 128 * HH;
    const bf16* AL = g_WkTL + cb + (size_t)by * 128 * HH;
    const bf16* BH = g_WqTH + cb + (size_t)bx * 256 * HH;
    const bf16* BL = g_WqTL + cb + (size_t)bx * 256 * HH;

    const int arow = tid >> 2, aq = tid & 3;
    const uint32_t sAOff = (uint32_t)(arow * SRB + aq * 32);
    const size_t gAOff = (size_t)arow * HH + aq * 16 + KB;
    const int brow = tid >> 1, bhalf = tid & 1;
    const uint32_t sBOff = (uint32_t)(brow * SRB + bhalf * 64);
    const size_t gBOff = (size_t)brow * HH + bhalf * 32 + KB;

    const int wm = wid >> 3, wn = wid & 7;
    const uint32_t aOff = (uint32_t)((wm * 64 + (lane & 15)) * SRB + ((lane >> 4) << 4));
    const uint32_t bOff = (uint32_t)((wn * 32 + (lane & 7) + ((lane >> 4) & 1) * 8) * SRB +
                                     (((lane >> 3) & 1) << 4));

    float acc[4][4][4] = {};

    {
#pragma unroll
        for (int i = 0; i < 2; i++) {
            CPA(sb + OFF_AH + sAOff + i * 16, AH + gAOff + i * 8);
            CPA(sb + OFF_AL + sAOff + i * 16, AL + gAOff + i * 8);
        }
#pragma unroll
        for (int i = 0; i < 4; i++) {
            CPA(sb + OFF_BH + sBOff + i * 16, BH + gBOff + i * 8);
            CPA(sb + OFF_BL + sBOff + i * 16, BL + gBOff + i * 8);
        }
        CPA_COMMIT();
    }

    for (int ck = 0; ck < NCH; ck++) {
        if (ck + 1 < NCH) {
            const uint32_t stg = sb + ((ck + 1) & 1) * STGB;
            const int kof = (ck + 1) * 64;
#pragma unroll
            for (int i = 0; i < 2; i++) {
                CPA(stg + OFF_AH + sAOff + i * 16, AH + gAOff + kof + i * 8);
                CPA(stg + OFF_AL + sAOff + i * 16, AL + gAOff + kof + i * 8);
            }
#pragma unroll
            for (int i = 0; i < 4; i++) {
                CPA(stg + OFF_BH + sBOff + i * 16, BH + gBOff + kof + i * 8);
                CPA(stg + OFF_BL + sBOff + i * 16, BL + gBOff + kof + i * 8);
            }
            CPA_COMMIT();
            CPA_WAIT1();
        } else {
            CPA_WAIT0();
        }
        __syncthreads();

        const uint32_t base = sb + (ck & 1) * STGB;
        const uint32_t pAH = base + OFF_AH + aOff, pAL = base + OFF_AL + aOff;
        const uint32_t pBH = base + OFF_BH + bOff, pBL = base + OFF_BL + bOff;
#pragma unroll
        for (int ka = 0; ka < 4; ka++) {
            uint32_t A[4][4], Bh[2][4], Bl[2][4];
#pragma unroll
            for (int m = 0; m < 4; m++) ldsm4(A[m], pAH + m * (16 * SRB) + ka * 32);
#pragma unroll
            for (int nb = 0; nb < 2; nb++) ldsm4(Bh[nb], pBH + nb * (16 * SRB) + ka * 32);
#pragma unroll
            for (int m = 0; m < 4; m++)
#pragma unroll
                for (int n8 = 0; n8 < 4; n8++)
                    mma_bf16(acc[m][n8], A[m], Bh[n8 >> 1][(n8 & 1) * 2], Bh[n8 >> 1][(n8 & 1) * 2 + 1]);
#pragma unroll
            for (int nb = 0; nb < 2; nb++) ldsm4(Bl[nb], pBL + nb * (16 * SRB) + ka * 32);
#pragma unroll
            for (int m = 0; m < 4; m++)
#pragma unroll
                for (int n8 = 0; n8 < 4; n8++)
                    mma_bf16(acc[m][n8], A[m], Bl[n8 >> 1][(n8 & 1) * 2], Bl[n8 >> 1][(n8 & 1) * 2 + 1]);
#pragma unroll
            for (int m = 0; m < 4; m++) ldsm4(A[m], pAL + m * (16 * SRB) + ka * 32);
#pragma unroll
            for (int m = 0; m < 4; m++)
#pragma unroll
                for (int n8 = 0; n8 < 4; n8++)
                    mma_bf16(acc[m][n8], A[m], Bh[n8 >> 1][(n8 & 1) * 2], Bh[n8 >> 1][(n8 & 1) * 2 + 1]);
        }
        __syncthreads();
    }

    // epilogue -> fp32 partials
    const int rBase = wm * 64 + (lane >> 2);
    const int cBase = wn * 32 + (lane & 3) * 2;
    float* P = g_McP + (size_t)kh * MCN + cb + (size_t)(by * 128) * HH;
#pragma unroll
    for (int m = 0; m < 4; m++) {
        int r0 = m * 16 + rBase;
#pragma unroll
        for (int n8 = 0; n8 < 4; n8++) {
            int cc = bx * 256 + cBase + n8 * 8;
            *(float2*)&P[(size_t)r0 * HH + cc] = make_float2(acc[m][n8][0], acc[m][n8][1]);
            *(float2*)&P[(size_t)(r0 + 8) * HH + cc] = make_float2(acc[m][n8][2], acc[m][n8][3]);
        }
    }
}

// combine split-K partials -> fp16
__global__ void k_mccvt() {
    size_t i = ((size_t)blockIdx.x * 256 + threadIdx.x) * 4;
    float4 a = *(float4*)&g_McP[i];
    float4 b = *(float4*)&g_McP[MCN + i];
    *(uint32_t*)&g_McTf[i] = packh(a.x + b.x, a.y + b.y);
    *(uint32_t*)&g_McTf[i + 2] = packh(a.z + b.z, a.w + b.w);
}

// ------------------------------ fp16 GEMM ---------------------------------
// OM 0: T = hidF . McTf^T            (grid: x=HH/128, y=BB*SS/128, z=CC)
// OM 1: out = ([Tf;EPf].hidF^T)*vsum (grid: x=SS/128, y=17, z=CC*BB)
// OM 2: E = embF . WkTf^T            (grid: x=HH/128, y=1, z=CC)
// CTA tile 128x128, 8 warps (2x4), warp tile 64x32, K-chunk 64, 3-stage,
// 2 CTAs/SM; single __syncthreads per chunk; B frags double-buffered.
template <int OM>
__global__ void __launch_bounds__(NTF, 2) k_fp16(float* __restrict__ out) {
    extern __shared__ __align__(128) char smem[];
    const uint32_t sb = smem_to_u32(smem);
    const int tid = threadIdx.x, wid = tid >> 5, lane = tid & 31;
    const int bx = blockIdx.x, by = blockIdx.y, bz = blockIdx.z;
    const int c = (OM == 1) ? (bz >> 4) : bz;
    const int b = (OM == 1) ? (bz & 15) : 0;

    const fp16 *Af, *Bf;
    if (OM == 0) {
        Af = g_hidF + (size_t)by * 128 * HH;
        Bf = g_McTf + (size_t)bz * HH * HH + (size_t)bx * 128 * HH;
    } else if (OM == 2) {
        Af = g_embF + (size_t)bz * 128 * HH;
        Bf = g_WkTf + (size_t)bz * HH * HH + (size_t)bx * 128 * HH;
    } else {
        Af = (by < 16)
            ? g_Tf + ((size_t)c * BB * SS + (size_t)b * SS + (size_t)by * 128) * HH
            : g_EPf + (size_t)c * 128 * HH;
        Bf = g_hidF + ((size_t)b * SS + (size_t)bx * 128) * HH;
    }

    const int lrow = tid >> 1, lhalf = tid & 1;
    const uint32_t sLOff = (uint32_t)(lrow * SRB + lhalf * 64);
    const size_t gLOff = (size_t)lrow * HH + lhalf * 32;

    const int wm = wid >> 2, wn = wid & 3;
    const uint32_t aOff = (uint32_t)((wm * 64 + (lane & 15)) * SRB + ((lane >> 4) << 4));
    const uint32_t bOff = (uint32_t)(OFF_BF + (wn * 32 + (lane & 7) + ((lane >> 4) & 1) * 8) * SRB +
                                     (((lane >> 3) & 1) << 4));

    float acc[4][4][4] = {};

#pragma unroll
    for (int pc = 0; pc < 2; pc++) {
        const uint32_t stg = sb + pc * STG_F;
        const int kof = pc * 64;
#pragma unroll
        for (int i = 0; i < 4; i++) {
            CPA(stg + sLOff + i * 16, Af + gLOff + kof + i * 8);
            CPA(stg + OFF_BF + sLOff + i * 16, Bf + gLOff + kof + i * 8);
        }
        CPA_COMMIT();
    }

    int stage = 0;
    for (int ck = 0; ck < NC; ck++) {
        if (ck + 1 < NC) CPA_WAIT1(); else CPA_WAIT0();
        __syncthreads();

        if (ck + 2 < NC) {
            int s2 = stage + 2; if (s2 >= NSTG_F) s2 -= NSTG_F;
            const uint32_t stg = sb + s2 * STG_F;
            const int kof = (ck + 2) * 64;
#pragma unroll
            for (int i = 0; i < 4; i++) {
                CPA(stg + sLOff + i * 16, Af + gLOff + kof + i * 8);
                CPA(stg + OFF_BF + sLOff + i * 16, Bf + gLOff + kof + i * 8);
            }
            CPA_COMMIT();
        }

        const uint32_t pA = sb + stage * STG_F + aOff;
        const uint32_t pB = sb + stage * STG_F + bOff;

        uint32_t Bq[2][2][4];
#pragma unroll
        for (int nb = 0; nb < 2; nb++) ldsm4(Bq[0][nb], pB + nb * (16 * SRB));
#pragma unroll
        for (int ka = 0; ka < 4; ka++) {
            const int cur = ka & 1, nxt = cur ^ 1;
            if (ka < 3) {
                const uint32_t ko = (ka + 1) * 32;
#pragma unroll
                for (int nb = 0; nb < 2; nb++) ldsm4(Bq[nxt][nb], pB + nb * (16 * SRB) + ko);
            }
            uint32_t A[4][4];
#pragma unroll
            for (int m = 0; m < 4; m++) ldsm4(A[m], pA + m * (16 * SRB) + ka * 32);
#pragma unroll
            for (int m = 0; m < 4; m++)
#pragma unroll
                for (int n8 = 0; n8 < 4; n8++)
                    mma_fp16(acc[m][n8], A[m],
                             Bq[cur][n8 >> 1][(n8 & 1) * 2], Bq[cur][n8 >> 1][(n8 & 1) * 2 + 1]);
        }
        if (++stage == NSTG_F) stage = 0;
    }

    // ------------------------------ epilogue --------------------------------
    const int rBase = wm * 64 + (lane >> 2);
    const int cBase = wn * 32 + (lane & 3) * 2;
    if (OM == 0 || OM == 2) {
        fp16* O = (OM == 0) ? g_Tf : g_EPf;
        size_t rowB = (OM == 0) ? ((size_t)bz * BB * SS + (size_t)by * 128) * HH
                                : (size_t)bz * 128 * HH;
#pragma unroll
        for (int m = 0; m < 4; m++) {
            int r0 = m * 16 + rBase;
#pragma unroll
            for (int n8 = 0; n8 < 4; n8++) {
                int cc = bx * 128 + cBase + n8 * 8;
                *(uint32_t*)&O[rowB + (size_t)r0 * HH + cc] = packh(acc[m][n8][0], acc[m][n8][1]);
                *(uint32_t*)&O[rowB + (size_t)(r0 + 8) * HH + cc] = packh(acc[m][n8][2], acc[m][n8][3]);
            }
        }
    } else {
        const float* vsp = g_vsum + ((size_t)c * BB + b) * SS + bx * 128;
        float* ob = out + ((size_t)b * CC + c) * SF * SS;
#pragma unroll
        for (int m = 0; m < 4; m++) {
            int r0 = by * 128 + m * 16 + rBase;
#pragma unroll
            for (int n8 = 0; n8 < 4; n8++) {
                int cc = cBase + n8 * 8;
                float2 vs = *(const float2*)(vsp + cc);
                size_t col = (size_t)bx * 128 + cc;
                if (r0 < SF) {
                    float2 o;
                    o.x = acc[m][n8][0] * vs.x;
                    o.y = acc[m][n8][1] * vs.y;
                    *(float2*)(ob + (size_t)r0 * SS + col) = o;
                }
                if (r0 + 8 < SF) {
                    float2 o;
                    o.x = acc[m][n8][2] * vs.x;
                    o.y = acc[m][n8][3] * vs.y;
                    *(float2*)(ob + (size_t)(r0 + 8) * SS + col) = o;
                }
            }
        }
    }
}

// ------------------------------ launch ------------------------------------
extern "C" void kernel_launch(void* const* d_in, const int* in_sizes, int n_in,
                              void* d_out, int out_size) {
    const float* hidden = (const float*)d_in[0];
    const float* emb    = (const float*)d_in[1];
    const float* Wk     = (const float*)d_in[2];
    const float* Wq     = (const float*)d_in[3];
    const float* Wv     = (const float*)d_in[4];
    float* out = (float*)d_out;

    cudaFuncSetAttribute(k_gemm, cudaFuncAttributeMaxDynamicSharedMemorySize, SMEM_G);
    cudaFuncSetAttribute(k_fp16<0>, cudaFuncAttributeMaxDynamicSharedMemorySize, SMEM_F);
    cudaFuncSetAttribute(k_fp16<1>, cudaFuncAttributeMaxDynamicSharedMemorySize, SMEM_F);
    cudaFuncSetAttribute(k_fp16<2>, cudaFuncAttributeMaxDynamicSharedMemorySize, SMEM_F);

    k_wvsum<<<dim3(HH / 256, CC), 256>>>(Wv);                      // 1
    k_cvt<<<CVT_HID_BLOCKS + 64, 256>>>(hidden, emb);              // 2 (hidF + vsum + embF)
    k_tsplit_both<<<dim3(32, 32, 2 * CC), dim3(32, 8)>>>(Wq, Wk);  // 3 (+WkTf)
    k_gemm<<<dim3(4, 8, CC * 2), NT, SMEM_G>>>();                  // 4: McT split-K  <- ncu
    k_mccvt<<<(int)(MCN / 1024), 256>>>();                         // 5: combine
    k_fp16<0><<<dim3(8, 256, CC), NTF, SMEM_F>>>(nullptr);         // 6: T
    k_fp16<2><<<dim3(8, 1, CC), NTF, SMEM_F>>>(nullptr);           // 7: E (fp16)
    k_fp16<1><<<dim3(16, 17, CC * BB), NTF, SMEM_F>>>(out);        // 8: scores
}